// round 13
// baseline (speedup 1.0000x reference)
#include <cuda_runtime.h>
#include <cuda_bf16.h>
#include <math.h>
#include <stdint.h>

// ---------------------------------------------------------------------------
// Problem constants
// ---------------------------------------------------------------------------
static constexpr int Bn = 8, Cn = 64, Hn = 256, Wn = 256;
static constexpr int HWn  = Hn * Wn;       // 65536
static constexpr int CHWn = Cn * HWn;      // 4194304
static constexpr int NZ   = Bn * Cn;       // 512
static constexpr int NTOT = 33554432;      // B*C*H*W

// ---------------------------------------------------------------------------
// Scratch (device globals: allocation-free contract)
// ---------------------------------------------------------------------------
__device__ __nv_bfloat16 g_qh[NTOT], g_ql[NTOT];
__device__ __nv_bfloat16 g_kh[NTOT], g_kl[NTOT];
__device__ __nv_bfloat16 g_vh[NTOT], g_vl[NTOT];
__device__ float         g_attn[NTOT];                 // fp32 logits [z][i][j]
__device__ __nv_bfloat16 g_ah[NTOT], g_al[NTOT];       // softmaxed attn split
__device__ __nv_bfloat16 g_Wh[3 * 4096], g_Wl[3 * 4096];  // pre-split weights

// ---------------------------------------------------------------------------
// PTX helpers — sm_80-era features only (compile clean at .target sm_103)
// ---------------------------------------------------------------------------
__device__ __forceinline__ uint32_t smem_to_u32(const void* p) {
    uint32_t a;
    asm("{ .reg .u64 t; cvta.to.shared.u64 t, %1; cvt.u32.u64 %0, t; }"
        : "=r"(a) : "l"(p));
    return a;
}

__device__ __forceinline__ void cp16(uint32_t s, const void* g) {
    asm volatile("cp.async.cg.shared.global [%0], [%1], 16;"
                 :: "r"(s), "l"(g) : "memory");
}
__device__ __forceinline__ void cp_commit() {
    asm volatile("cp.async.commit_group;" ::: "memory");
}
template <int N>
__device__ __forceinline__ void cp_wait() {
    asm volatile("cp.async.wait_group %0;" :: "n"(N) : "memory");
}

__device__ __forceinline__ void ldsm_x4(uint32_t* r, uint32_t addr) {
    asm volatile("ldmatrix.sync.aligned.m8n8.x4.shared.b16 {%0,%1,%2,%3}, [%4];"
                 : "=r"(r[0]), "=r"(r[1]), "=r"(r[2]), "=r"(r[3]) : "r"(addr));
}
__device__ __forceinline__ void ldsm_x4_t(uint32_t* r, uint32_t addr) {
    asm volatile("ldmatrix.sync.aligned.m8n8.x4.trans.shared.b16 {%0,%1,%2,%3}, [%4];"
                 : "=r"(r[0]), "=r"(r[1]), "=r"(r[2]), "=r"(r[3]) : "r"(addr));
}

__device__ __forceinline__ void mma16816(float* c, const uint32_t* a, const uint32_t* b) {
    asm volatile(
        "mma.sync.aligned.m16n8k16.row.col.f32.bf16.bf16.f32 "
        "{%0,%1,%2,%3}, {%4,%5,%6,%7}, {%8,%9}, {%0,%1,%2,%3};"
        : "+f"(c[0]), "+f"(c[1]), "+f"(c[2]), "+f"(c[3])
        : "r"(a[0]), "r"(a[1]), "r"(a[2]), "r"(a[3]), "r"(b[0]), "r"(b[1]));
}

__device__ __forceinline__ void split_bf16(float x, __nv_bfloat16& hi, __nv_bfloat16& lo) {
    hi = __float2bfloat16(x);
    lo = __float2bfloat16(x - __bfloat162float(hi));
}

// ---------------------------------------------------------------------------
// Kernel W: one-time split of Wq/Wk/Wv into bf16 hi/lo (3 x 64 x 64)
// ---------------------------------------------------------------------------
__global__ void __launch_bounds__(256) wsplit_kernel(
    const float* __restrict__ Wq, const float* __restrict__ Wk,
    const float* __restrict__ Wv)
{
    const int t = blockIdx.x * 256 + threadIdx.x;
    if (t >= 3 * 4096) return;
    const int m = t >> 12, i = t & 4095;
    const float* src = (m == 0) ? Wq : (m == 1) ? Wk : Wv;
    __nv_bfloat16 hi, lo;
    split_bf16(src[i], hi, lo);
    g_Wh[t] = hi;
    g_Wl[t] = lo;
}

// ---------------------------------------------------------------------------
// Kernel A: tensor-core 1x1 conv. Per CTA: batch b, 128 pixels, all 3 mats.
// M=o(64) x N=p(128) x K=c(64).
//   A = W fragments built DIRECTLY from pre-split gmem (no smem, no syncs):
//       mma m16n8k16 A layout: a0=A[g][2tg..+1], a1=A[g+8][2tg..+1],
//                              a2=A[g][2tg+8..+9], a3=A[g+8][2tg+8..+9]
//       -> one 4B bf16x2 load per reg from g_Wh/g_Wl (L1/L2 broadcast).
//   B = x[c][p] K-major, pitch 136 (272B, proven GEMM-B mapping) -> ldsm trans
// Only 2 __syncthreads() per CTA (X staging). Term-major mma ordering.
// smem: 2 x 64 x 136 x 2B = 34,816 B static.
// ---------------------------------------------------------------------------
__global__ void __launch_bounds__(256, 2) qkv_mma_kernel(
    const float* __restrict__ x,
    const float* __restrict__ bq, const float* __restrict__ bk,
    const float* __restrict__ bv)
{
    constexpr int XP = 136;

    __shared__ __align__(16) __nv_bfloat16 Xh[64 * XP], Xl[64 * XP];
    const uint32_t sXh = smem_to_u32(Xh), sXl = smem_to_u32(Xl);

    const int t    = threadIdx.x;
    const int lane = t & 31;
    const int wid  = t >> 5;
    const int b    = blockIdx.y;
    const int p0   = blockIdx.x * 128;

    // --- stage x tile [c=64][p=128], split to hi/lo (32 pixels/thread) ---
    {
        const int c  = t >> 2;          // 0..63
        const int pg = (t & 3) * 32;    // 0,32,64,96
        const float* xrow = x + ((size_t)(b * Cn + c)) * HWn + p0 + pg;
        #pragma unroll
        for (int blk = 0; blk < 4; blk++) {
            __nv_bfloat16 hb[8], lb[8];
            #pragma unroll
            for (int j = 0; j < 8; j += 4) {
                float4 v4 = *reinterpret_cast<const float4*>(xrow + blk * 8 + j);
                split_bf16(v4.x, hb[j + 0], lb[j + 0]);
                split_bf16(v4.y, hb[j + 1], lb[j + 1]);
                split_bf16(v4.z, hb[j + 2], lb[j + 2]);
                split_bf16(v4.w, hb[j + 3], lb[j + 3]);
            }
            *reinterpret_cast<uint4*>(&Xh[c * XP + pg + blk * 8]) =
                *reinterpret_cast<uint4*>(hb);
            *reinterpret_cast<uint4*>(&Xl[c * XP + pg + blk * 8]) =
                *reinterpret_cast<uint4*>(lb);
        }
    }
    __syncthreads();   // X visible CTA-wide (the ONLY barrier needed)

    const float* biases[3] = {bq, bk, bv};
    __nv_bfloat16* outs_hi[3] = {g_qh, g_kh, g_vh};
    __nv_bfloat16* outs_lo[3] = {g_ql, g_kl, g_vl};

    const int mw = (wid & 3) * 16;   // o-offset of warp (4 warps over M=64)
    const int nw = (wid >> 2) * 64;  // p-offset of warp (2 warps over N=128)
    const int g  = lane >> 2;
    const int tg = lane & 3;

    // A-fragment gmem offsets (in elements), constant across ks except col
    const int r0e = (mw + g) * 64;
    const int r1e = (mw + 8 + g) * 64;

    #pragma unroll
    for (int m = 0; m < 3; m++) {
        const __nv_bfloat16* WhP = g_Wh + m * 4096;
        const __nv_bfloat16* WlP = g_Wl + m * 4096;

        float acc[8][4] = {};
        #pragma unroll
        for (int ks = 0; ks < 4; ks++) {
            const int c0 = ks * 16 + 2 * tg;
            const int c1 = c0 + 8;
            uint32_t ah[4], al[4];
            ah[0] = *reinterpret_cast<const uint32_t*>(WhP + r0e + c0);
            ah[1] = *reinterpret_cast<const uint32_t*>(WhP + r1e + c0);
            ah[2] = *reinterpret_cast<const uint32_t*>(WhP + r0e + c1);
            ah[3] = *reinterpret_cast<const uint32_t*>(WhP + r1e + c1);
            al[0] = *reinterpret_cast<const uint32_t*>(WlP + r0e + c0);
            al[1] = *reinterpret_cast<const uint32_t*>(WlP + r1e + c0);
            al[2] = *reinterpret_cast<const uint32_t*>(WlP + r0e + c1);
            al[3] = *reinterpret_cast<const uint32_t*>(WlP + r1e + c1);

            uint32_t bh[4][4], bl[4][4];
            #pragma unroll
            for (int np = 0; np < 4; np++) {
                int kk = ks * 16 + (lane & 7) + ((lane >> 3) & 1) * 8;
                int nn = nw + np * 16 + ((lane >> 4) & 1) * 8;
                uint32_t rel = (uint32_t)((kk * XP + nn) * 2);
                ldsm_x4_t(bh[np], sXh + rel);
                ldsm_x4_t(bl[np], sXl + rel);
            }
            // term-major: consecutive mma hit different accumulators
            #pragma unroll
            for (int np = 0; np < 4; np++)
                #pragma unroll
                for (int h = 0; h < 2; h++)
                    mma16816(acc[np * 2 + h], ah, bh[np] + 2 * h);
            #pragma unroll
            for (int np = 0; np < 4; np++)
                #pragma unroll
                for (int h = 0; h < 2; h++)
                    mma16816(acc[np * 2 + h], ah, bl[np] + 2 * h);
            #pragma unroll
            for (int np = 0; np < 4; np++)
                #pragma unroll
                for (int h = 0; h < 2; h++)
                    mma16816(acc[np * 2 + h], al, bh[np] + 2 * h);
        }

        // epilogue: bias add, split, store bf16x2 pairs (consecutive pixels)
        const float* bias = biases[m];
        const float bo0 = bias[mw + g];
        const float bo1 = bias[mw + 8 + g];
        __nv_bfloat16* dh = outs_hi[m];
        __nv_bfloat16* dl = outs_lo[m];
        const size_t row0 = (size_t)(b * Cn + mw + g) * HWn + p0;
        const size_t row1 = (size_t)(b * Cn + mw + 8 + g) * HWn + p0;
        #pragma unroll
        for (int nj = 0; nj < 8; nj++) {
            const int p = nw + nj * 8 + tg * 2;
            __nv_bfloat16 h0, l0, h1, l1;
            split_bf16(acc[nj][0] + bo0, h0, l0);
            split_bf16(acc[nj][1] + bo0, h1, l1);
            __nv_bfloat162 hp, lp;
            hp.x = h0; hp.y = h1; lp.x = l0; lp.y = l1;
            *reinterpret_cast<__nv_bfloat162*>(dh + row0 + p) = hp;
            *reinterpret_cast<__nv_bfloat162*>(dl + row0 + p) = lp;
            split_bf16(acc[nj][2] + bo1, h0, l0);
            split_bf16(acc[nj][3] + bo1, h1, l1);
            hp.x = h0; hp.y = h1; lp.x = l0; lp.y = l1;
            *reinterpret_cast<__nv_bfloat162*>(dh + row1 + p) = hp;
            *reinterpret_cast<__nv_bfloat162*>(dl + row1 + p) = lp;
        }
    }
}

// ---------------------------------------------------------------------------
// Kernel B1: qtk GEMM. attn[z,i,j] = sum_h q[z,h,i] k[z,h,j].
// 128x128 CTA tile, K-chunks of 16, cp.async double-buffered static smem.
// Term-major mma ordering (acc reuse distance = 4 mma).
// ---------------------------------------------------------------------------
__global__ void __launch_bounds__(256, 2) gemm_qtk_kernel()
{
    constexpr int OFF_AL = 4352;      // A tile: [16][136] bf16 = 4352 B
    constexpr int OFF_BH = 8704;
    constexpr int OFF_BL = 13056;
    constexpr int STAGE  = 17408;

    __shared__ __align__(16) char smem[2 * STAGE];
    const uint32_t sb = smem_to_u32(smem);

    const int t    = threadIdx.x;
    const int lane = t & 31;
    const int wid  = t >> 5;
    const int z    = blockIdx.y;
    const int m0   = (blockIdx.x & 1) * 128;
    const int n0   = (blockIdx.x >> 1) * 128;
    const size_t zoff = (size_t)z * HWn;

    const __nv_bfloat16* pAh = g_qh + zoff;
    const __nv_bfloat16* pAl = g_ql + zoff;
    const __nv_bfloat16* pBh = g_kh + zoff;
    const __nv_bfloat16* pBl = g_kl + zoff;

    const int mw = (wid & 3) * 32;
    const int nw = (wid >> 2) * 64;

    float acc[2][8][4] = {};

    auto copy_chunk = [&](int kc, int stg) {
        const uint32_t s0 = sb + (uint32_t)stg * STAGE;
        const int k0  = kc * 16;
        const int row = t >> 4;
        const int c   = t & 15;
        const uint32_t so = (uint32_t)(row * 272 + c * 16);
        cp16(s0 + so,          pAh + (size_t)(k0 + row) * Wn + m0 + c * 8);
        cp16(s0 + OFF_AL + so, pAl + (size_t)(k0 + row) * Wn + m0 + c * 8);
        cp16(s0 + OFF_BH + so, pBh + (size_t)(k0 + row) * Wn + n0 + c * 8);
        cp16(s0 + OFF_BL + so, pBl + (size_t)(k0 + row) * Wn + n0 + c * 8);
    };

    auto compute = [&](int stg) {
        const uint32_t s0 = sb + (uint32_t)stg * STAGE;
        uint32_t ah[2][4], al[2][4];
        #pragma unroll
        for (int mt = 0; mt < 2; mt++) {
            int kk = (lane & 7) + ((lane >> 4) << 3);
            int mm = mw + mt * 16 + ((lane >> 3) & 1) * 8;
            uint32_t rel = (uint32_t)(kk * 272 + mm * 2);
            ldsm_x4_t(ah[mt], s0 + rel);
            ldsm_x4_t(al[mt], s0 + OFF_AL + rel);
        }
        #pragma unroll
        for (int np = 0; np < 4; np++) {
            int kk = (lane & 7) + ((lane >> 3) & 1) * 8;
            int nn = nw + np * 16 + ((lane >> 4) & 1) * 8;
            uint32_t rel = (uint32_t)(kk * 272 + nn * 2);
            uint32_t bh[4], bl[4];
            ldsm_x4_t(bh, s0 + OFF_BH + rel);
            ldsm_x4_t(bl, s0 + OFF_BL + rel);
            #pragma unroll
            for (int mt = 0; mt < 2; mt++)
                #pragma unroll
                for (int h = 0; h < 2; h++)
                    mma16816(acc[mt][np * 2 + h], ah[mt], bh + 2 * h);
            #pragma unroll
            for (int mt = 0; mt < 2; mt++)
                #pragma unroll
                for (int h = 0; h < 2; h++)
                    mma16816(acc[mt][np * 2 + h], ah[mt], bl + 2 * h);
            #pragma unroll
            for (int mt = 0; mt < 2; mt++)
                #pragma unroll
                for (int h = 0; h < 2; h++)
                    mma16816(acc[mt][np * 2 + h], al[mt], bh + 2 * h);
        }
    };

    copy_chunk(0, 0);
    cp_commit();
    for (int kc = 0; kc < 16; kc++) {
        cp_wait<0>();
        __syncthreads();
        if (kc < 15) { copy_chunk(kc + 1, (kc + 1) & 1); cp_commit(); }
        compute(kc & 1);
    }

    const int g  = lane >> 2;
    const int tg = lane & 3;
    #pragma unroll
    for (int mt = 0; mt < 2; mt++) {
        const int r0 = m0 + mw + mt * 16 + g;
        #pragma unroll
        for (int nj = 0; nj < 8; nj++) {
            const int col = n0 + nw + nj * 8 + tg * 2;
            *reinterpret_cast<float2*>(g_attn + zoff + (size_t)r0 * Wn + col) =
                make_float2(acc[mt][nj][0], acc[mt][nj][1]);
            *reinterpret_cast<float2*>(g_attn + zoff + (size_t)(r0 + 8) * Wn + col) =
                make_float2(acc[mt][nj][2], acc[mt][nj][3]);
        }
    }
}

// ---------------------------------------------------------------------------
// Kernel B2: av GEMM. out[z,i,j] = sum_m attn[z,i,m] v[z,m,j].
// ---------------------------------------------------------------------------
__global__ void __launch_bounds__(256, 2) gemm_av_kernel(float* __restrict__ out)
{
    constexpr int APITCH = 48;
    constexpr int OFF_AL = 6144;
    constexpr int OFF_BH = 12288;
    constexpr int OFF_BL = 16640;
    constexpr int STAGE  = 20992;

    __shared__ __align__(16) char smem[2 * STAGE];
    const uint32_t sb = smem_to_u32(smem);

    const int t    = threadIdx.x;
    const int lane = t & 31;
    const int wid  = t >> 5;
    const int z    = blockIdx.y;
    const int m0   = (blockIdx.x & 1) * 128;
    const int n0   = (blockIdx.x >> 1) * 128;
    const size_t zoff = (size_t)z * HWn;

    const __nv_bfloat16* pAh = g_ah + zoff;
    const __nv_bfloat16* pAl = g_al + zoff;
    const __nv_bfloat16* pBh = g_vh + zoff;
    const __nv_bfloat16* pBl = g_vl + zoff;

    const int mw = (wid & 3) * 32;
    const int nw = (wid >> 2) * 64;

    float acc[2][8][4] = {};

    auto copy_chunk = [&](int kc, int stg) {
        const uint32_t s0 = sb + (uint32_t)stg * STAGE;
        const int k0 = kc * 16;
        {
            const int row = t >> 1;
            const int c   = t & 1;
            const uint32_t so = (uint32_t)(row * APITCH + c * 16);
            cp16(s0 + so,          pAh + (size_t)(m0 + row) * Wn + k0 + c * 8);
            cp16(s0 + OFF_AL + so, pAl + (size_t)(m0 + row) * Wn + k0 + c * 8);
        }
        {
            const int row = t >> 4;
            const int c   = t & 15;
            const uint32_t so = (uint32_t)(row * 272 + c * 16);
            cp16(s0 + OFF_BH + so, pBh + (size_t)(k0 + row) * Wn + n0 + c * 8);
            cp16(s0 + OFF_BL + so, pBl + (size_t)(k0 + row) * Wn + n0 + c * 8);
        }
    };

    auto compute = [&](int stg) {
        const uint32_t s0 = sb + (uint32_t)stg * STAGE;
        uint32_t ah[2][4], al[2][4];
        #pragma unroll
        for (int mt = 0; mt < 2; mt++) {
            int mm = mw + mt * 16 + (lane & 15);
            int kk = ((lane >> 4) & 1) * 8;
            uint32_t rel = (uint32_t)(mm * APITCH + kk * 2);
            ldsm_x4(ah[mt], s0 + rel);
            ldsm_x4(al[mt], s0 + OFF_AL + rel);
        }
        #pragma unroll
        for (int np = 0; np < 4; np++) {
            int kk = (lane & 7) + ((lane >> 3) & 1) * 8;
            int nn = nw + np * 16 + ((lane >> 4) & 1) * 8;
            uint32_t rel = (uint32_t)(kk * 272 + nn * 2);
            uint32_t bh[4], bl[4];
            ldsm_x4_t(bh, s0 + OFF_BH + rel);
            ldsm_x4_t(bl, s0 + OFF_BL + rel);
            #pragma unroll
            for (int mt = 0; mt < 2; mt++)
                #pragma unroll
                for (int h = 0; h < 2; h++)
                    mma16816(acc[mt][np * 2 + h], ah[mt], bh + 2 * h);
            #pragma unroll
            for (int mt = 0; mt < 2; mt++)
                #pragma unroll
                for (int h = 0; h < 2; h++)
                    mma16816(acc[mt][np * 2 + h], ah[mt], bl + 2 * h);
            #pragma unroll
            for (int mt = 0; mt < 2; mt++)
                #pragma unroll
                for (int h = 0; h < 2; h++)
                    mma16816(acc[mt][np * 2 + h], al[mt], bh + 2 * h);
        }
    };

    copy_chunk(0, 0);
    cp_commit();
    for (int kc = 0; kc < 16; kc++) {
        cp_wait<0>();
        __syncthreads();
        if (kc < 15) { copy_chunk(kc + 1, (kc + 1) & 1); cp_commit(); }
        compute(kc & 1);
    }

    const int g  = lane >> 2;
    const int tg = lane & 3;
    #pragma unroll
    for (int mt = 0; mt < 2; mt++) {
        const int r0 = m0 + mw + mt * 16 + g;
        #pragma unroll
        for (int nj = 0; nj < 8; nj++) {
            const int col = n0 + nw + nj * 8 + tg * 2;
            *reinterpret_cast<float2*>(out + zoff + (size_t)r0 * Wn + col) =
                make_float2(acc[mt][nj][0], acc[mt][nj][1]);
            *reinterpret_cast<float2*>(out + zoff + (size_t)(r0 + 8) * Wn + col) =
                make_float2(acc[mt][nj][2], acc[mt][nj][3]);
        }
    }
}

// ---------------------------------------------------------------------------
// Kernel C: softmax over channel axis (fp32 in, bf16 hi/lo out)
// ---------------------------------------------------------------------------
__global__ void __launch_bounds__(256) softmax_split_kernel()
{
    const int idx = blockIdx.x * 256 + threadIdx.x;   // 0 .. B*HW-1
    const int b   = idx >> 16;
    const int ij  = idx & 65535;
    const size_t base = (size_t)b * CHWn + ij;

    float v[64];
    float mx = -INFINITY;
    #pragma unroll
    for (int c = 0; c < 64; c++) {
        v[c] = g_attn[base + (size_t)c * HWn];
        mx = fmaxf(mx, v[c]);
    }
    float s = 0.0f;
    #pragma unroll
    for (int c = 0; c < 64; c++) {
        v[c] = expf(v[c] - mx);
        s += v[c];
    }
    const float inv = 1.0f / s;
    #pragma unroll
    for (int c = 0; c < 64; c++) {
        float p = v[c] * inv;
        __nv_bfloat16 hi, lo;
        split_bf16(p, hi, lo);
        g_ah[base + (size_t)c * HWn] = hi;
        g_al[base + (size_t)c * HWn] = lo;
    }
}

// ---------------------------------------------------------------------------
// Launch — no dynamic smem, no attribute calls, plain default-stream launches.
// ---------------------------------------------------------------------------
extern "C" void kernel_launch(void* const* d_in, const int* in_sizes, int n_in,
                              void* d_out, int out_size)
{
    const float* x  = (const float*)d_in[0];
    const float* Wq = (const float*)d_in[1];
    const float* bq = (const float*)d_in[2];
    const float* Wk = (const float*)d_in[3];
    const float* bk = (const float*)d_in[4];
    const float* Wv = (const float*)d_in[5];
    const float* bv = (const float*)d_in[6];
    float* out = (float*)d_out;

    // 0) split weights to bf16 hi/lo (tiny)
    wsplit_kernel<<<48, 256>>>(Wq, Wk, Wv);

    // 1) q,k,v = 1x1 conv(x) on tensor cores, W frags direct from gmem
    qkv_mma_kernel<<<dim3(HWn / 128, Bn), 256>>>(x, bq, bk, bv);

    // 2) attn logits: attn[z,i,j] = sum_h q[z,h,i] k[z,h,j]
    gemm_qtk_kernel<<<dim3(4, NZ), 256>>>();

    // 3) softmax over channels, emit bf16 hi/lo ([i][m] row-major for next GEMM)
    softmax_split_kernel<<<(Bn * HWn) / 256, 256>>>();

    // 4) out[z,i,j] = sum_m attn[z,i,m] v[z,m,j]
    gemm_av_kernel<<<dim3(4, NZ), 256>>>(out);
}

// round 14
// speedup vs baseline: 1.1063x; 1.1063x over previous
#include <cuda_runtime.h>
#include <cuda_bf16.h>
#include <math.h>
#include <stdint.h>

// ---------------------------------------------------------------------------
// Problem constants
// ---------------------------------------------------------------------------
static constexpr int Bn = 8, Cn = 64, Hn = 256, Wn = 256;
static constexpr int HWn  = Hn * Wn;       // 65536
static constexpr int CHWn = Cn * HWn;      // 4194304
static constexpr int NZ   = Bn * Cn;       // 512
static constexpr int NTOT = 33554432;      // B*C*H*W

// ---------------------------------------------------------------------------
// Scratch (device globals: allocation-free contract)
// ---------------------------------------------------------------------------
__device__ __nv_bfloat16 g_qh[NTOT], g_ql[NTOT];
__device__ __nv_bfloat16 g_kh[NTOT], g_kl[NTOT];
__device__ __nv_bfloat16 g_vh[NTOT], g_vl[NTOT];
__device__ float         g_attn[NTOT];                 // fp32 logits [z][i][j]
__device__ __nv_bfloat16 g_ah[NTOT], g_al[NTOT];       // softmaxed attn split
__device__ __nv_bfloat16 g_Wh[3 * 4096], g_Wl[3 * 4096];  // pre-split weights

// ---------------------------------------------------------------------------
// PTX helpers — sm_80-era features only (compile clean at .target sm_103)
// ---------------------------------------------------------------------------
__device__ __forceinline__ uint32_t smem_to_u32(const void* p) {
    uint32_t a;
    asm("{ .reg .u64 t; cvta.to.shared.u64 t, %1; cvt.u32.u64 %0, t; }"
        : "=r"(a) : "l"(p));
    return a;
}

__device__ __forceinline__ void cp16(uint32_t s, const void* g) {
    asm volatile("cp.async.cg.shared.global [%0], [%1], 16;"
                 :: "r"(s), "l"(g) : "memory");
}
__device__ __forceinline__ void cp_commit() {
    asm volatile("cp.async.commit_group;" ::: "memory");
}
template <int N>
__device__ __forceinline__ void cp_wait() {
    asm volatile("cp.async.wait_group %0;" :: "n"(N) : "memory");
}

__device__ __forceinline__ void ldsm_x4(uint32_t* r, uint32_t addr) {
    asm volatile("ldmatrix.sync.aligned.m8n8.x4.shared.b16 {%0,%1,%2,%3}, [%4];"
                 : "=r"(r[0]), "=r"(r[1]), "=r"(r[2]), "=r"(r[3]) : "r"(addr));
}
__device__ __forceinline__ void ldsm_x4_t(uint32_t* r, uint32_t addr) {
    asm volatile("ldmatrix.sync.aligned.m8n8.x4.trans.shared.b16 {%0,%1,%2,%3}, [%4];"
                 : "=r"(r[0]), "=r"(r[1]), "=r"(r[2]), "=r"(r[3]) : "r"(addr));
}

__device__ __forceinline__ void mma16816(float* c, const uint32_t* a, const uint32_t* b) {
    asm volatile(
        "mma.sync.aligned.m16n8k16.row.col.f32.bf16.bf16.f32 "
        "{%0,%1,%2,%3}, {%4,%5,%6,%7}, {%8,%9}, {%0,%1,%2,%3};"
        : "+f"(c[0]), "+f"(c[1]), "+f"(c[2]), "+f"(c[3])
        : "r"(a[0]), "r"(a[1]), "r"(a[2]), "r"(a[3]), "r"(b[0]), "r"(b[1]));
}

__device__ __forceinline__ void split_bf16(float x, __nv_bfloat16& hi, __nv_bfloat16& lo) {
    hi = __float2bfloat16(x);
    lo = __float2bfloat16(x - __bfloat162float(hi));
}

// ---------------------------------------------------------------------------
// Kernel W: one-time split of Wq/Wk/Wv into bf16 hi/lo (3 x 64 x 64)
// ---------------------------------------------------------------------------
__global__ void __launch_bounds__(256) wsplit_kernel(
    const float* __restrict__ Wq, const float* __restrict__ Wk,
    const float* __restrict__ Wv)
{
    const int t = blockIdx.x * 256 + threadIdx.x;
    if (t >= 3 * 4096) return;
    const int m = t >> 12, i = t & 4095;
    const float* src = (m == 0) ? Wq : (m == 1) ? Wk : Wv;
    __nv_bfloat16 hi, lo;
    split_bf16(src[i], hi, lo);
    g_Wh[t] = hi;
    g_Wl[t] = lo;
}

// ---------------------------------------------------------------------------
// Kernel A: tensor-core 1x1 conv (r12 structure). Per CTA: batch b, 64 px,
// all 3 matrices. M=o(64) x N=p(64) x K=c(64).
//   A = W[o][c] row-major, pitch 72 -> non-trans ldmatrix.
//       W staged from PRE-SPLIT gmem via cp.async (4 x 16B per thread).
//   B = x[c][p] K-major, pitch 72 -> trans ldmatrix.
// Term-major mma ordering.
// ---------------------------------------------------------------------------
__global__ void __launch_bounds__(256) qkv_mma_kernel(
    const float* __restrict__ x,
    const float* __restrict__ bq, const float* __restrict__ bk,
    const float* __restrict__ bv)
{
    constexpr int XP = 72;   // pitch in elems (144 B)
    constexpr int WP = 72;

    __shared__ __align__(16) __nv_bfloat16 Xh[64 * XP], Xl[64 * XP];
    __shared__ __align__(16) __nv_bfloat16 Wh[64 * WP], Wl[64 * WP];

    const uint32_t sXh = smem_to_u32(Xh), sXl = smem_to_u32(Xl);
    const uint32_t sWh = smem_to_u32(Wh), sWl = smem_to_u32(Wl);

    const int t    = threadIdx.x;
    const int lane = t & 31;
    const int wid  = t >> 5;
    const int b    = blockIdx.y;
    const int p0   = blockIdx.x * 64;

    // --- stage x tile [c=64][p=64], split to hi/lo ---
    {
        const int c  = t >> 2;          // 0..63
        const int pg = (t & 3) * 16;    // 0,16,32,48
        const float* xrow = x + ((size_t)(b * Cn + c)) * HWn + p0 + pg;
        __nv_bfloat16 hb[16], lb[16];
        #pragma unroll
        for (int j = 0; j < 16; j += 4) {
            float4 v4 = *reinterpret_cast<const float4*>(xrow + j);
            split_bf16(v4.x, hb[j + 0], lb[j + 0]);
            split_bf16(v4.y, hb[j + 1], lb[j + 1]);
            split_bf16(v4.z, hb[j + 2], lb[j + 2]);
            split_bf16(v4.w, hb[j + 3], lb[j + 3]);
        }
        *reinterpret_cast<uint4*>(&Xh[c * XP + pg])     = reinterpret_cast<uint4*>(hb)[0];
        *reinterpret_cast<uint4*>(&Xh[c * XP + pg + 8]) = reinterpret_cast<uint4*>(hb)[1];
        *reinterpret_cast<uint4*>(&Xl[c * XP + pg])     = reinterpret_cast<uint4*>(lb)[0];
        *reinterpret_cast<uint4*>(&Xl[c * XP + pg + 8]) = reinterpret_cast<uint4*>(lb)[1];
    }

    const float* biases[3] = {bq, bk, bv};
    __nv_bfloat16* outs_hi[3] = {g_qh, g_kh, g_vh};
    __nv_bfloat16* outs_lo[3] = {g_ql, g_kl, g_vl};

    const int mw = (wid & 3) * 16;   // o-offset of warp
    const int nw = (wid >> 2) * 32;  // p-offset of warp
    const int g  = lane >> 2;
    const int tg = lane & 3;

    for (int m = 0; m < 3; m++) {
        __syncthreads();   // prior compute done before W overwrite
        {   // stage W[o][c] hi/lo via cp.async from pre-split gmem (4 x 16B)
            const int o  = t >> 2;
            const int cg = (t & 3) * 16;
            const uint32_t so = (uint32_t)((o * WP + cg) * 2);
            const __nv_bfloat16* wh = g_Wh + m * 4096 + o * 64 + cg;
            const __nv_bfloat16* wl = g_Wl + m * 4096 + o * 64 + cg;
            cp16(sWh + so,      wh);
            cp16(sWh + so + 16, wh + 8);
            cp16(sWl + so,      wl);
            cp16(sWl + so + 16, wl + 8);
            cp_commit();
            cp_wait<0>();
        }
        __syncthreads();   // W + X visible (covers X stores on m==0)

        float acc[4][4] = {};
        #pragma unroll
        for (int ks = 0; ks < 4; ks++) {
            uint32_t ah[4], al[4];
            {   // A = W rows (o), non-trans
                int mm = mw + (lane & 15);
                int kk = ks * 16 + ((lane >> 4) & 1) * 8;
                uint32_t rel = (uint32_t)((mm * WP + kk) * 2);
                ldsm_x4(ah, sWh + rel);
                ldsm_x4(al, sWl + rel);
            }
            uint32_t bh[2][4], bl[2][4];
            #pragma unroll
            for (int np = 0; np < 2; np++) {
                int kk = ks * 16 + (lane & 7) + ((lane >> 3) & 1) * 8;
                int nn = nw + np * 16 + ((lane >> 4) & 1) * 8;
                uint32_t rel = (uint32_t)((kk * XP + nn) * 2);
                ldsm_x4_t(bh[np], sXh + rel);
                ldsm_x4_t(bl[np], sXl + rel);
            }
            // term-major: consecutive mma target different accumulators
            #pragma unroll
            for (int np = 0; np < 2; np++)
                #pragma unroll
                for (int h = 0; h < 2; h++)
                    mma16816(acc[np * 2 + h], ah, bh[np] + 2 * h);
            #pragma unroll
            for (int np = 0; np < 2; np++)
                #pragma unroll
                for (int h = 0; h < 2; h++)
                    mma16816(acc[np * 2 + h], ah, bl[np] + 2 * h);
            #pragma unroll
            for (int np = 0; np < 2; np++)
                #pragma unroll
                for (int h = 0; h < 2; h++)
                    mma16816(acc[np * 2 + h], al, bh[np] + 2 * h);
        }

        // epilogue: bias add, split, store bf16x2 pairs (consecutive pixels)
        const float* bias = biases[m];
        const float bo0 = bias[mw + g];
        const float bo1 = bias[mw + 8 + g];
        __nv_bfloat16* dh = outs_hi[m];
        __nv_bfloat16* dl = outs_lo[m];
        const size_t row0 = (size_t)(b * Cn + mw + g) * HWn + p0;
        const size_t row1 = (size_t)(b * Cn + mw + 8 + g) * HWn + p0;
        #pragma unroll
        for (int nj = 0; nj < 4; nj++) {
            const int p = nw + nj * 8 + tg * 2;
            __nv_bfloat16 h0, l0, h1, l1;
            split_bf16(acc[nj][0] + bo0, h0, l0);
            split_bf16(acc[nj][1] + bo0, h1, l1);
            __nv_bfloat162 hp, lp;
            hp.x = h0; hp.y = h1; lp.x = l0; lp.y = l1;
            *reinterpret_cast<__nv_bfloat162*>(dh + row0 + p) = hp;
            *reinterpret_cast<__nv_bfloat162*>(dl + row0 + p) = lp;
            split_bf16(acc[nj][2] + bo1, h0, l0);
            split_bf16(acc[nj][3] + bo1, h1, l1);
            hp.x = h0; hp.y = h1; lp.x = l0; lp.y = l1;
            *reinterpret_cast<__nv_bfloat162*>(dh + row1 + p) = hp;
            *reinterpret_cast<__nv_bfloat162*>(dl + row1 + p) = lp;
        }
    }
}

// ---------------------------------------------------------------------------
// Kernel B1: qtk GEMM. attn[z,i,j] = sum_h q[z,h,i] k[z,h,j].
// 128x128 CTA tile, K-chunks of 16, cp.async double-buffered static smem.
// Term-major mma ordering (acc reuse distance = 4 mma).
// ---------------------------------------------------------------------------
__global__ void __launch_bounds__(256, 2) gemm_qtk_kernel()
{
    constexpr int OFF_AL = 4352;      // A tile: [16][136] bf16 = 4352 B
    constexpr int OFF_BH = 8704;
    constexpr int OFF_BL = 13056;
    constexpr int STAGE  = 17408;

    __shared__ __align__(16) char smem[2 * STAGE];
    const uint32_t sb = smem_to_u32(smem);

    const int t    = threadIdx.x;
    const int lane = t & 31;
    const int wid  = t >> 5;
    const int z    = blockIdx.y;
    const int m0   = (blockIdx.x & 1) * 128;
    const int n0   = (blockIdx.x >> 1) * 128;
    const size_t zoff = (size_t)z * HWn;

    const __nv_bfloat16* pAh = g_qh + zoff;
    const __nv_bfloat16* pAl = g_ql + zoff;
    const __nv_bfloat16* pBh = g_kh + zoff;
    const __nv_bfloat16* pBl = g_kl + zoff;

    const int mw = (wid & 3) * 32;
    const int nw = (wid >> 2) * 64;

    float acc[2][8][4] = {};

    auto copy_chunk = [&](int kc, int stg) {
        const uint32_t s0 = sb + (uint32_t)stg * STAGE;
        const int k0  = kc * 16;
        const int row = t >> 4;
        const int c   = t & 15;
        const uint32_t so = (uint32_t)(row * 272 + c * 16);
        cp16(s0 + so,          pAh + (size_t)(k0 + row) * Wn + m0 + c * 8);
        cp16(s0 + OFF_AL + so, pAl + (size_t)(k0 + row) * Wn + m0 + c * 8);
        cp16(s0 + OFF_BH + so, pBh + (size_t)(k0 + row) * Wn + n0 + c * 8);
        cp16(s0 + OFF_BL + so, pBl + (size_t)(k0 + row) * Wn + n0 + c * 8);
    };

    auto compute = [&](int stg) {
        const uint32_t s0 = sb + (uint32_t)stg * STAGE;
        uint32_t ah[2][4], al[2][4];
        #pragma unroll
        for (int mt = 0; mt < 2; mt++) {
            int kk = (lane & 7) + ((lane >> 4) << 3);
            int mm = mw + mt * 16 + ((lane >> 3) & 1) * 8;
            uint32_t rel = (uint32_t)(kk * 272 + mm * 2);
            ldsm_x4_t(ah[mt], s0 + rel);
            ldsm_x4_t(al[mt], s0 + OFF_AL + rel);
        }
        #pragma unroll
        for (int np = 0; np < 4; np++) {
            int kk = (lane & 7) + ((lane >> 3) & 1) * 8;
            int nn = nw + np * 16 + ((lane >> 4) & 1) * 8;
            uint32_t rel = (uint32_t)(kk * 272 + nn * 2);
            uint32_t bh[4], bl[4];
            ldsm_x4_t(bh, s0 + OFF_BH + rel);
            ldsm_x4_t(bl, s0 + OFF_BL + rel);
            #pragma unroll
            for (int mt = 0; mt < 2; mt++)
                #pragma unroll
                for (int h = 0; h < 2; h++)
                    mma16816(acc[mt][np * 2 + h], ah[mt], bh + 2 * h);
            #pragma unroll
            for (int mt = 0; mt < 2; mt++)
                #pragma unroll
                for (int h = 0; h < 2; h++)
                    mma16816(acc[mt][np * 2 + h], ah[mt], bl + 2 * h);
            #pragma unroll
            for (int mt = 0; mt < 2; mt++)
                #pragma unroll
                for (int h = 0; h < 2; h++)
                    mma16816(acc[mt][np * 2 + h], al[mt], bh + 2 * h);
        }
    };

    copy_chunk(0, 0);
    cp_commit();
    for (int kc = 0; kc < 16; kc++) {
        cp_wait<0>();
        __syncthreads();
        if (kc < 15) { copy_chunk(kc + 1, (kc + 1) & 1); cp_commit(); }
        compute(kc & 1);
    }

    const int g  = lane >> 2;
    const int tg = lane & 3;
    #pragma unroll
    for (int mt = 0; mt < 2; mt++) {
        const int r0 = m0 + mw + mt * 16 + g;
        #pragma unroll
        for (int nj = 0; nj < 8; nj++) {
            const int col = n0 + nw + nj * 8 + tg * 2;
            *reinterpret_cast<float2*>(g_attn + zoff + (size_t)r0 * Wn + col) =
                make_float2(acc[mt][nj][0], acc[mt][nj][1]);
            *reinterpret_cast<float2*>(g_attn + zoff + (size_t)(r0 + 8) * Wn + col) =
                make_float2(acc[mt][nj][2], acc[mt][nj][3]);
        }
    }
}

// ---------------------------------------------------------------------------
// Kernel B2: av GEMM. out[z,i,j] = sum_m attn[z,i,m] v[z,m,j].
// ---------------------------------------------------------------------------
__global__ void __launch_bounds__(256, 2) gemm_av_kernel(float* __restrict__ out)
{
    constexpr int APITCH = 48;
    constexpr int OFF_AL = 6144;
    constexpr int OFF_BH = 12288;
    constexpr int OFF_BL = 16640;
    constexpr int STAGE  = 20992;

    __shared__ __align__(16) char smem[2 * STAGE];
    const uint32_t sb = smem_to_u32(smem);

    const int t    = threadIdx.x;
    const int lane = t & 31;
    const int wid  = t >> 5;
    const int z    = blockIdx.y;
    const int m0   = (blockIdx.x & 1) * 128;
    const int n0   = (blockIdx.x >> 1) * 128;
    const size_t zoff = (size_t)z * HWn;

    const __nv_bfloat16* pAh = g_ah + zoff;
    const __nv_bfloat16* pAl = g_al + zoff;
    const __nv_bfloat16* pBh = g_vh + zoff;
    const __nv_bfloat16* pBl = g_vl + zoff;

    const int mw = (wid & 3) * 32;
    const int nw = (wid >> 2) * 64;

    float acc[2][8][4] = {};

    auto copy_chunk = [&](int kc, int stg) {
        const uint32_t s0 = sb + (uint32_t)stg * STAGE;
        const int k0 = kc * 16;
        {
            const int row = t >> 1;
            const int c   = t & 1;
            const uint32_t so = (uint32_t)(row * APITCH + c * 16);
            cp16(s0 + so,          pAh + (size_t)(m0 + row) * Wn + k0 + c * 8);
            cp16(s0 + OFF_AL + so, pAl + (size_t)(m0 + row) * Wn + k0 + c * 8);
        }
        {
            const int row = t >> 4;
            const int c   = t & 15;
            const uint32_t so = (uint32_t)(row * 272 + c * 16);
            cp16(s0 + OFF_BH + so, pBh + (size_t)(k0 + row) * Wn + n0 + c * 8);
            cp16(s0 + OFF_BL + so, pBl + (size_t)(k0 + row) * Wn + n0 + c * 8);
        }
    };

    auto compute = [&](int stg) {
        const uint32_t s0 = sb + (uint32_t)stg * STAGE;
        uint32_t ah[2][4], al[2][4];
        #pragma unroll
        for (int mt = 0; mt < 2; mt++) {
            int mm = mw + mt * 16 + (lane & 15);
            int kk = ((lane >> 4) & 1) * 8;
            uint32_t rel = (uint32_t)(mm * APITCH + kk * 2);
            ldsm_x4(ah[mt], s0 + rel);
            ldsm_x4(al[mt], s0 + OFF_AL + rel);
        }
        #pragma unroll
        for (int np = 0; np < 4; np++) {
            int kk = (lane & 7) + ((lane >> 3) & 1) * 8;
            int nn = nw + np * 16 + ((lane >> 4) & 1) * 8;
            uint32_t rel = (uint32_t)(kk * 272 + nn * 2);
            uint32_t bh[4], bl[4];
            ldsm_x4_t(bh, s0 + OFF_BH + rel);
            ldsm_x4_t(bl, s0 + OFF_BL + rel);
            #pragma unroll
            for (int mt = 0; mt < 2; mt++)
                #pragma unroll
                for (int h = 0; h < 2; h++)
                    mma16816(acc[mt][np * 2 + h], ah[mt], bh + 2 * h);
            #pragma unroll
            for (int mt = 0; mt < 2; mt++)
                #pragma unroll
                for (int h = 0; h < 2; h++)
                    mma16816(acc[mt][np * 2 + h], ah[mt], bl + 2 * h);
            #pragma unroll
            for (int mt = 0; mt < 2; mt++)
                #pragma unroll
                for (int h = 0; h < 2; h++)
                    mma16816(acc[mt][np * 2 + h], al[mt], bh + 2 * h);
        }
    };

    copy_chunk(0, 0);
    cp_commit();
    for (int kc = 0; kc < 16; kc++) {
        cp_wait<0>();
        __syncthreads();
        if (kc < 15) { copy_chunk(kc + 1, (kc + 1) & 1); cp_commit(); }
        compute(kc & 1);
    }

    const int g  = lane >> 2;
    const int tg = lane & 3;
    #pragma unroll
    for (int mt = 0; mt < 2; mt++) {
        const int r0 = m0 + mw + mt * 16 + g;
        #pragma unroll
        for (int nj = 0; nj < 8; nj++) {
            const int col = n0 + nw + nj * 8 + tg * 2;
            *reinterpret_cast<float2*>(out + zoff + (size_t)r0 * Wn + col) =
                make_float2(acc[mt][nj][0], acc[mt][nj][1]);
            *reinterpret_cast<float2*>(out + zoff + (size_t)(r0 + 8) * Wn + col) =
                make_float2(acc[mt][nj][2], acc[mt][nj][3]);
        }
    }
}

// ---------------------------------------------------------------------------
// Kernel C: softmax over channel axis (fp32 in, bf16 hi/lo out)
// ---------------------------------------------------------------------------
__global__ void __launch_bounds__(256) softmax_split_kernel()
{
    const int idx = blockIdx.x * 256 + threadIdx.x;   // 0 .. B*HW-1
    const int b   = idx >> 16;
    const int ij  = idx & 65535;
    const size_t base = (size_t)b * CHWn + ij;

    float v[64];
    float mx = -INFINITY;
    #pragma unroll
    for (int c = 0; c < 64; c++) {
        v[c] = g_attn[base + (size_t)c * HWn];
        mx = fmaxf(mx, v[c]);
    }
    float s = 0.0f;
    #pragma unroll
    for (int c = 0; c < 64; c++) {
        v[c] = expf(v[c] - mx);
        s += v[c];
    }
    const float inv = 1.0f / s;
    #pragma unroll
    for (int c = 0; c < 64; c++) {
        float p = v[c] * inv;
        __nv_bfloat16 hi, lo;
        split_bf16(p, hi, lo);
        g_ah[base + (size_t)c * HWn] = hi;
        g_al[base + (size_t)c * HWn] = lo;
    }
}

// ---------------------------------------------------------------------------
// Launch — no dynamic smem, no attribute calls, plain default-stream launches.
// ---------------------------------------------------------------------------
extern "C" void kernel_launch(void* const* d_in, const int* in_sizes, int n_in,
                              void* d_out, int out_size)
{
    const float* x  = (const float*)d_in[0];
    const float* Wq = (const float*)d_in[1];
    const float* bq = (const float*)d_in[2];
    const float* Wk = (const float*)d_in[3];
    const float* bk = (const float*)d_in[4];
    const float* Wv = (const float*)d_in[5];
    const float* bv = (const float*)d_in[6];
    float* out = (float*)d_out;

    // 0) split weights to bf16 hi/lo (tiny)
    wsplit_kernel<<<48, 256>>>(Wq, Wk, Wv);

    // 1) q,k,v = 1x1 conv(x) on tensor cores, W staged via cp.async
    qkv_mma_kernel<<<dim3(HWn / 64, Bn), 256>>>(x, bq, bk, bv);

    // 2) attn logits: attn[z,i,j] = sum_h q[z,h,i] k[z,h,j]
    gemm_qtk_kernel<<<dim3(4, NZ), 256>>>();

    // 3) softmax over channels, emit bf16 hi/lo ([i][m] row-major for next GEMM)
    softmax_split_kernel<<<(Bn * HWn) / 256, 256>>>();

    // 4) out[z,i,j] = sum_m attn[z,i,m] v[z,m,j]
    gemm_av_kernel<<<dim3(4, NZ), 256>>>(out);
}

// round 15
// speedup vs baseline: 1.1072x; 1.0008x over previous
#include <cuda_runtime.h>
#include <cuda_bf16.h>
#include <math.h>
#include <stdint.h>

// ---------------------------------------------------------------------------
// Problem constants
// ---------------------------------------------------------------------------
static constexpr int Bn = 8, Cn = 64, Hn = 256, Wn = 256;
static constexpr int HWn  = Hn * Wn;       // 65536
static constexpr int CHWn = Cn * HWn;      // 4194304
static constexpr int NZ   = Bn * Cn;       // 512
static constexpr int NTOT = 33554432;      // B*C*H*W

// ---------------------------------------------------------------------------
// Scratch (device globals: allocation-free contract)
// ---------------------------------------------------------------------------
__device__ __nv_bfloat16 g_qh[NTOT], g_ql[NTOT];
__device__ __nv_bfloat16 g_kh[NTOT], g_kl[NTOT];
__device__ __nv_bfloat16 g_vh[NTOT], g_vl[NTOT];
__device__ float         g_attn[NTOT];                 // fp32 logits [z][i][j]
__device__ __nv_bfloat16 g_ah[NTOT], g_al[NTOT];       // softmaxed attn split
__device__ __nv_bfloat16 g_Wh[3 * 4096], g_Wl[3 * 4096];  // pre-split weights

// ---------------------------------------------------------------------------
// PTX helpers — sm_80-era features only (compile clean at .target sm_103)
// ---------------------------------------------------------------------------
__device__ __forceinline__ uint32_t smem_to_u32(const void* p) {
    uint32_t a;
    asm("{ .reg .u64 t; cvta.to.shared.u64 t, %1; cvt.u32.u64 %0, t; }"
        : "=r"(a) : "l"(p));
    return a;
}

__device__ __forceinline__ void cp16(uint32_t s, const void* g) {
    asm volatile("cp.async.cg.shared.global [%0], [%1], 16;"
                 :: "r"(s), "l"(g) : "memory");
}
__device__ __forceinline__ void cp_commit() {
    asm volatile("cp.async.commit_group;" ::: "memory");
}
template <int N>
__device__ __forceinline__ void cp_wait() {
    asm volatile("cp.async.wait_group %0;" :: "n"(N) : "memory");
}

__device__ __forceinline__ void ldsm_x4(uint32_t* r, uint32_t addr) {
    asm volatile("ldmatrix.sync.aligned.m8n8.x4.shared.b16 {%0,%1,%2,%3}, [%4];"
                 : "=r"(r[0]), "=r"(r[1]), "=r"(r[2]), "=r"(r[3]) : "r"(addr));
}
__device__ __forceinline__ void ldsm_x4_t(uint32_t* r, uint32_t addr) {
    asm volatile("ldmatrix.sync.aligned.m8n8.x4.trans.shared.b16 {%0,%1,%2,%3}, [%4];"
                 : "=r"(r[0]), "=r"(r[1]), "=r"(r[2]), "=r"(r[3]) : "r"(addr));
}

__device__ __forceinline__ void mma16816(float* c, const uint32_t* a, const uint32_t* b) {
    asm volatile(
        "mma.sync.aligned.m16n8k16.row.col.f32.bf16.bf16.f32 "
        "{%0,%1,%2,%3}, {%4,%5,%6,%7}, {%8,%9}, {%0,%1,%2,%3};"
        : "+f"(c[0]), "+f"(c[1]), "+f"(c[2]), "+f"(c[3])
        : "r"(a[0]), "r"(a[1]), "r"(a[2]), "r"(a[3]), "r"(b[0]), "r"(b[1]));
}

__device__ __forceinline__ void split_bf16(float x, __nv_bfloat16& hi, __nv_bfloat16& lo) {
    hi = __float2bfloat16(x);
    lo = __float2bfloat16(x - __bfloat162float(hi));
}

// ---------------------------------------------------------------------------
// Kernel W: one-time split of Wq/Wk/Wv into bf16 hi/lo (3 x 64 x 64)
// ---------------------------------------------------------------------------
__global__ void __launch_bounds__(256) wsplit_kernel(
    const float* __restrict__ Wq, const float* __restrict__ Wk,
    const float* __restrict__ Wv)
{
    const int t = blockIdx.x * 256 + threadIdx.x;
    if (t >= 3 * 4096) return;
    const int m = t >> 12, i = t & 4095;
    const float* src = (m == 0) ? Wq : (m == 1) ? Wk : Wv;
    __nv_bfloat16 hi, lo;
    split_bf16(src[i], hi, lo);
    g_Wh[t] = hi;
    g_Wl[t] = lo;
}

// ---------------------------------------------------------------------------
// Kernel A: tensor-core 1x1 conv. Per CTA: batch b, 64 px, all 3 matrices.
// M=o(64) x N=p(64) x K=c(64).
//   A = W[o][c] row-major, pitch 72 -> non-trans ldmatrix.
//       W staged from PRE-SPLIT gmem via cp.async (4 x 16B per thread).
//   B = x[c][p] K-major, pitch 72 -> trans ldmatrix.
// Term-major mma ordering. min-blocks=3 (85-reg cap) for latency hiding:
// smem 36,864 B/CTA allows 3 CTAs/SM; the per-CTA path is serial, so
// occupancy is the only in-budget lever.
// ---------------------------------------------------------------------------
__global__ void __launch_bounds__(256, 3) qkv_mma_kernel(
    const float* __restrict__ x,
    const float* __restrict__ bq, const float* __restrict__ bk,
    const float* __restrict__ bv)
{
    constexpr int XP = 72;   // pitch in elems (144 B)
    constexpr int WP = 72;

    __shared__ __align__(16) __nv_bfloat16 Xh[64 * XP], Xl[64 * XP];
    __shared__ __align__(16) __nv_bfloat16 Wh[64 * WP], Wl[64 * WP];

    const uint32_t sXh = smem_to_u32(Xh), sXl = smem_to_u32(Xl);
    const uint32_t sWh = smem_to_u32(Wh), sWl = smem_to_u32(Wl);

    const int t    = threadIdx.x;
    const int lane = t & 31;
    const int wid  = t >> 5;
    const int b    = blockIdx.y;
    const int p0   = blockIdx.x * 64;

    // --- stage x tile [c=64][p=64], split to hi/lo ---
    {
        const int c  = t >> 2;          // 0..63
        const int pg = (t & 3) * 16;    // 0,16,32,48
        const float* xrow = x + ((size_t)(b * Cn + c)) * HWn + p0 + pg;
        __nv_bfloat16 hb[16], lb[16];
        #pragma unroll
        for (int j = 0; j < 16; j += 4) {
            float4 v4 = *reinterpret_cast<const float4*>(xrow + j);
            split_bf16(v4.x, hb[j + 0], lb[j + 0]);
            split_bf16(v4.y, hb[j + 1], lb[j + 1]);
            split_bf16(v4.z, hb[j + 2], lb[j + 2]);
            split_bf16(v4.w, hb[j + 3], lb[j + 3]);
        }
        *reinterpret_cast<uint4*>(&Xh[c * XP + pg])     = reinterpret_cast<uint4*>(hb)[0];
        *reinterpret_cast<uint4*>(&Xh[c * XP + pg + 8]) = reinterpret_cast<uint4*>(hb)[1];
        *reinterpret_cast<uint4*>(&Xl[c * XP + pg])     = reinterpret_cast<uint4*>(lb)[0];
        *reinterpret_cast<uint4*>(&Xl[c * XP + pg + 8]) = reinterpret_cast<uint4*>(lb)[1];
    }

    const int mw = (wid & 3) * 16;   // o-offset of warp
    const int nw = (wid >> 2) * 32;  // p-offset of warp
    const int g  = lane >> 2;
    const int tg = lane & 3;

    #pragma unroll
    for (int m = 0; m < 3; m++) {
        const float* bias =
            (m == 0) ? bq : (m == 1) ? bk : bv;
        __nv_bfloat16* dh = (m == 0) ? g_qh : (m == 1) ? g_kh : g_vh;
        __nv_bfloat16* dl = (m == 0) ? g_ql : (m == 1) ? g_kl : g_vl;

        __syncthreads();   // prior compute done before W overwrite
        {   // stage W[o][c] hi/lo via cp.async from pre-split gmem (4 x 16B)
            const int o  = t >> 2;
            const int cg = (t & 3) * 16;
            const uint32_t so = (uint32_t)((o * WP + cg) * 2);
            const __nv_bfloat16* wh = g_Wh + m * 4096 + o * 64 + cg;
            const __nv_bfloat16* wl = g_Wl + m * 4096 + o * 64 + cg;
            cp16(sWh + so,      wh);
            cp16(sWh + so + 16, wh + 8);
            cp16(sWl + so,      wl);
            cp16(sWl + so + 16, wl + 8);
            cp_commit();
            cp_wait<0>();
        }
        __syncthreads();   // W + X visible (covers X stores on m==0)

        float acc[4][4] = {};
        #pragma unroll
        for (int ks = 0; ks < 4; ks++) {
            uint32_t ah[4], al[4];
            {   // A = W rows (o), non-trans
                int mm = mw + (lane & 15);
                int kk = ks * 16 + ((lane >> 4) & 1) * 8;
                uint32_t rel = (uint32_t)((mm * WP + kk) * 2);
                ldsm_x4(ah, sWh + rel);
                ldsm_x4(al, sWl + rel);
            }
            uint32_t bh[2][4], bl[2][4];
            #pragma unroll
            for (int np = 0; np < 2; np++) {
                int kk = ks * 16 + (lane & 7) + ((lane >> 3) & 1) * 8;
                int nn = nw + np * 16 + ((lane >> 4) & 1) * 8;
                uint32_t rel = (uint32_t)((kk * XP + nn) * 2);
                ldsm_x4_t(bh[np], sXh + rel);
                ldsm_x4_t(bl[np], sXl + rel);
            }
            // term-major: consecutive mma target different accumulators
            #pragma unroll
            for (int np = 0; np < 2; np++)
                #pragma unroll
                for (int h = 0; h < 2; h++)
                    mma16816(acc[np * 2 + h], ah, bh[np] + 2 * h);
            #pragma unroll
            for (int np = 0; np < 2; np++)
                #pragma unroll
                for (int h = 0; h < 2; h++)
                    mma16816(acc[np * 2 + h], ah, bl[np] + 2 * h);
            #pragma unroll
            for (int np = 0; np < 2; np++)
                #pragma unroll
                for (int h = 0; h < 2; h++)
                    mma16816(acc[np * 2 + h], al, bh[np] + 2 * h);
        }

        // epilogue: bias add, split, store bf16x2 pairs (consecutive pixels)
        const float bo0 = bias[mw + g];
        const float bo1 = bias[mw + 8 + g];
        const size_t row0 = (size_t)(b * Cn + mw + g) * HWn + p0;
        const size_t row1 = (size_t)(b * Cn + mw + 8 + g) * HWn + p0;
        #pragma unroll
        for (int nj = 0; nj < 4; nj++) {
            const int p = nw + nj * 8 + tg * 2;
            __nv_bfloat16 h0, l0, h1, l1;
            split_bf16(acc[nj][0] + bo0, h0, l0);
            split_bf16(acc[nj][1] + bo0, h1, l1);
            __nv_bfloat162 hp, lp;
            hp.x = h0; hp.y = h1; lp.x = l0; lp.y = l1;
            *reinterpret_cast<__nv_bfloat162*>(dh + row0 + p) = hp;
            *reinterpret_cast<__nv_bfloat162*>(dl + row0 + p) = lp;
            split_bf16(acc[nj][2] + bo1, h0, l0);
            split_bf16(acc[nj][3] + bo1, h1, l1);
            hp.x = h0; hp.y = h1; lp.x = l0; lp.y = l1;
            *reinterpret_cast<__nv_bfloat162*>(dh + row1 + p) = hp;
            *reinterpret_cast<__nv_bfloat162*>(dl + row1 + p) = lp;
        }
    }
}

// ---------------------------------------------------------------------------
// Kernel B1: qtk GEMM. attn[z,i,j] = sum_h q[z,h,i] k[z,h,j].
// 128x128 CTA tile, K-chunks of 16, cp.async double-buffered static smem.
// Term-major mma ordering (acc reuse distance = 4 mma).
// ---------------------------------------------------------------------------
__global__ void __launch_bounds__(256, 2) gemm_qtk_kernel()
{
    constexpr int OFF_AL = 4352;      // A tile: [16][136] bf16 = 4352 B
    constexpr int OFF_BH = 8704;
    constexpr int OFF_BL = 13056;
    constexpr int STAGE  = 17408;

    __shared__ __align__(16) char smem[2 * STAGE];
    const uint32_t sb = smem_to_u32(smem);

    const int t    = threadIdx.x;
    const int lane = t & 31;
    const int wid  = t >> 5;
    const int z    = blockIdx.y;
    const int m0   = (blockIdx.x & 1) * 128;
    const int n0   = (blockIdx.x >> 1) * 128;
    const size_t zoff = (size_t)z * HWn;

    const __nv_bfloat16* pAh = g_qh + zoff;
    const __nv_bfloat16* pAl = g_ql + zoff;
    const __nv_bfloat16* pBh = g_kh + zoff;
    const __nv_bfloat16* pBl = g_kl + zoff;

    const int mw = (wid & 3) * 32;
    const int nw = (wid >> 2) * 64;

    float acc[2][8][4] = {};

    auto copy_chunk = [&](int kc, int stg) {
        const uint32_t s0 = sb + (uint32_t)stg * STAGE;
        const int k0  = kc * 16;
        const int row = t >> 4;
        const int c   = t & 15;
        const uint32_t so = (uint32_t)(row * 272 + c * 16);
        cp16(s0 + so,          pAh + (size_t)(k0 + row) * Wn + m0 + c * 8);
        cp16(s0 + OFF_AL + so, pAl + (size_t)(k0 + row) * Wn + m0 + c * 8);
        cp16(s0 + OFF_BH + so, pBh + (size_t)(k0 + row) * Wn + n0 + c * 8);
        cp16(s0 + OFF_BL + so, pBl + (size_t)(k0 + row) * Wn + n0 + c * 8);
    };

    auto compute = [&](int stg) {
        const uint32_t s0 = sb + (uint32_t)stg * STAGE;
        uint32_t ah[2][4], al[2][4];
        #pragma unroll
        for (int mt = 0; mt < 2; mt++) {
            int kk = (lane & 7) + ((lane >> 4) << 3);
            int mm = mw + mt * 16 + ((lane >> 3) & 1) * 8;
            uint32_t rel = (uint32_t)(kk * 272 + mm * 2);
            ldsm_x4_t(ah[mt], s0 + rel);
            ldsm_x4_t(al[mt], s0 + OFF_AL + rel);
        }
        #pragma unroll
        for (int np = 0; np < 4; np++) {
            int kk = (lane & 7) + ((lane >> 3) & 1) * 8;
            int nn = nw + np * 16 + ((lane >> 4) & 1) * 8;
            uint32_t rel = (uint32_t)(kk * 272 + nn * 2);
            uint32_t bh[4], bl[4];
            ldsm_x4_t(bh, s0 + OFF_BH + rel);
            ldsm_x4_t(bl, s0 + OFF_BL + rel);
            #pragma unroll
            for (int mt = 0; mt < 2; mt++)
                #pragma unroll
                for (int h = 0; h < 2; h++)
                    mma16816(acc[mt][np * 2 + h], ah[mt], bh + 2 * h);
            #pragma unroll
            for (int mt = 0; mt < 2; mt++)
                #pragma unroll
                for (int h = 0; h < 2; h++)
                    mma16816(acc[mt][np * 2 + h], ah[mt], bl + 2 * h);
            #pragma unroll
            for (int mt = 0; mt < 2; mt++)
                #pragma unroll
                for (int h = 0; h < 2; h++)
                    mma16816(acc[mt][np * 2 + h], al[mt], bh + 2 * h);
        }
    };

    copy_chunk(0, 0);
    cp_commit();
    for (int kc = 0; kc < 16; kc++) {
        cp_wait<0>();
        __syncthreads();
        if (kc < 15) { copy_chunk(kc + 1, (kc + 1) & 1); cp_commit(); }
        compute(kc & 1);
    }

    const int g  = lane >> 2;
    const int tg = lane & 3;
    #pragma unroll
    for (int mt = 0; mt < 2; mt++) {
        const int r0 = m0 + mw + mt * 16 + g;
        #pragma unroll
        for (int nj = 0; nj < 8; nj++) {
            const int col = n0 + nw + nj * 8 + tg * 2;
            *reinterpret_cast<float2*>(g_attn + zoff + (size_t)r0 * Wn + col) =
                make_float2(acc[mt][nj][0], acc[mt][nj][1]);
            *reinterpret_cast<float2*>(g_attn + zoff + (size_t)(r0 + 8) * Wn + col) =
                make_float2(acc[mt][nj][2], acc[mt][nj][3]);
        }
    }
}

// ---------------------------------------------------------------------------
// Kernel B2: av GEMM. out[z,i,j] = sum_m attn[z,i,m] v[z,m,j].
// ---------------------------------------------------------------------------
__global__ void __launch_bounds__(256, 2) gemm_av_kernel(float* __restrict__ out)
{
    constexpr int APITCH = 48;
    constexpr int OFF_AL = 6144;
    constexpr int OFF_BH = 12288;
    constexpr int OFF_BL = 16640;
    constexpr int STAGE  = 20992;

    __shared__ __align__(16) char smem[2 * STAGE];
    const uint32_t sb = smem_to_u32(smem);

    const int t    = threadIdx.x;
    const int lane = t & 31;
    const int wid  = t >> 5;
    const int z    = blockIdx.y;
    const int m0   = (blockIdx.x & 1) * 128;
    const int n0   = (blockIdx.x >> 1) * 128;
    const size_t zoff = (size_t)z * HWn;

    const __nv_bfloat16* pAh = g_ah + zoff;
    const __nv_bfloat16* pAl = g_al + zoff;
    const __nv_bfloat16* pBh = g_vh + zoff;
    const __nv_bfloat16* pBl = g_vl + zoff;

    const int mw = (wid & 3) * 32;
    const int nw = (wid >> 2) * 64;

    float acc[2][8][4] = {};

    auto copy_chunk = [&](int kc, int stg) {
        const uint32_t s0 = sb + (uint32_t)stg * STAGE;
        const int k0 = kc * 16;
        {
            const int row = t >> 1;
            const int c   = t & 1;
            const uint32_t so = (uint32_t)(row * APITCH + c * 16);
            cp16(s0 + so,          pAh + (size_t)(m0 + row) * Wn + k0 + c * 8);
            cp16(s0 + OFF_AL + so, pAl + (size_t)(m0 + row) * Wn + k0 + c * 8);
        }
        {
            const int row = t >> 4;
            const int c   = t & 15;
            const uint32_t so = (uint32_t)(row * 272 + c * 16);
            cp16(s0 + OFF_BH + so, pBh + (size_t)(k0 + row) * Wn + n0 + c * 8);
            cp16(s0 + OFF_BL + so, pBl + (size_t)(k0 + row) * Wn + n0 + c * 8);
        }
    };

    auto compute = [&](int stg) {
        const uint32_t s0 = sb + (uint32_t)stg * STAGE;
        uint32_t ah[2][4], al[2][4];
        #pragma unroll
        for (int mt = 0; mt < 2; mt++) {
            int mm = mw + mt * 16 + (lane & 15);
            int kk = ((lane >> 4) & 1) * 8;
            uint32_t rel = (uint32_t)(mm * APITCH + kk * 2);
            ldsm_x4(ah[mt], s0 + rel);
            ldsm_x4(al[mt], s0 + OFF_AL + rel);
        }
        #pragma unroll
        for (int np = 0; np < 4; np++) {
            int kk = (lane & 7) + ((lane >> 3) & 1) * 8;
            int nn = nw + np * 16 + ((lane >> 4) & 1) * 8;
            uint32_t rel = (uint32_t)(kk * 272 + nn * 2);
            uint32_t bh[4], bl[4];
            ldsm_x4_t(bh, s0 + OFF_BH + rel);
            ldsm_x4_t(bl, s0 + OFF_BL + rel);
            #pragma unroll
            for (int mt = 0; mt < 2; mt++)
                #pragma unroll
                for (int h = 0; h < 2; h++)
                    mma16816(acc[mt][np * 2 + h], ah[mt], bh + 2 * h);
            #pragma unroll
            for (int mt = 0; mt < 2; mt++)
                #pragma unroll
                for (int h = 0; h < 2; h++)
                    mma16816(acc[mt][np * 2 + h], ah[mt], bl + 2 * h);
            #pragma unroll
            for (int mt = 0; mt < 2; mt++)
                #pragma unroll
                for (int h = 0; h < 2; h++)
                    mma16816(acc[mt][np * 2 + h], al[mt], bh + 2 * h);
        }
    };

    copy_chunk(0, 0);
    cp_commit();
    for (int kc = 0; kc < 16; kc++) {
        cp_wait<0>();
        __syncthreads();
        if (kc < 15) { copy_chunk(kc + 1, (kc + 1) & 1); cp_commit(); }
        compute(kc & 1);
    }

    const int g  = lane >> 2;
    const int tg = lane & 3;
    #pragma unroll
    for (int mt = 0; mt < 2; mt++) {
        const int r0 = m0 + mw + mt * 16 + g;
        #pragma unroll
        for (int nj = 0; nj < 8; nj++) {
            const int col = n0 + nw + nj * 8 + tg * 2;
            *reinterpret_cast<float2*>(out + zoff + (size_t)r0 * Wn + col) =
                make_float2(acc[mt][nj][0], acc[mt][nj][1]);
            *reinterpret_cast<float2*>(out + zoff + (size_t)(r0 + 8) * Wn + col) =
                make_float2(acc[mt][nj][2], acc[mt][nj][3]);
        }
    }
}

// ---------------------------------------------------------------------------
// Kernel C: softmax over channel axis (fp32 in, bf16 hi/lo out)
// ---------------------------------------------------------------------------
__global__ void __launch_bounds__(256) softmax_split_kernel()
{
    const int idx = blockIdx.x * 256 + threadIdx.x;   // 0 .. B*HW-1
    const int b   = idx >> 16;
    const int ij  = idx & 65535;
    const size_t base = (size_t)b * CHWn + ij;

    float v[64];
    float mx = -INFINITY;
    #pragma unroll
    for (int c = 0; c < 64; c++) {
        v[c] = g_attn[base + (size_t)c * HWn];
        mx = fmaxf(mx, v[c]);
    }
    float s = 0.0f;
    #pragma unroll
    for (int c = 0; c < 64; c++) {
        v[c] = __expf(v[c] - mx);
        s += v[c];
    }
    const float inv = 1.0f / s;
    #pragma unroll
    for (int c = 0; c < 64; c++) {
        float p = v[c] * inv;
        __nv_bfloat16 hi, lo;
        split_bf16(p, hi, lo);
        g_ah[base + (size_t)c * HWn] = hi;
        g_al[base + (size_t)c * HWn] = lo;
    }
}

// ---------------------------------------------------------------------------
// Launch — no dynamic smem, no attribute calls, plain default-stream launches.
// ---------------------------------------------------------------------------
extern "C" void kernel_launch(void* const* d_in, const int* in_sizes, int n_in,
                              void* d_out, int out_size)
{
    const float* x  = (const float*)d_in[0];
    const float* Wq = (const float*)d_in[1];
    const float* bq = (const float*)d_in[2];
    const float* Wk = (const float*)d_in[3];
    const float* bk = (const float*)d_in[4];
    const float* Wv = (const float*)d_in[5];
    const float* bv = (const float*)d_in[6];
    float* out = (float*)d_out;

    // 0) split weights to bf16 hi/lo (tiny)
    wsplit_kernel<<<48, 256>>>(Wq, Wk, Wv);

    // 1) q,k,v = 1x1 conv(x) on tensor cores, W staged via cp.async
    qkv_mma_kernel<<<dim3(HWn / 64, Bn), 256>>>(x, bq, bk, bv);

    // 2) attn logits: attn[z,i,j] = sum_h q[z,h,i] k[z,h,j]
    gemm_qtk_kernel<<<dim3(4, NZ), 256>>>();

    // 3) softmax over channels, emit bf16 hi/lo ([i][m] row-major for next GEMM)
    softmax_split_kernel<<<(Bn * HWn) / 256, 256>>>();

    // 4) out[z,i,j] = sum_m attn[z,i,m] v[z,m,j]
    gemm_av_kernel<<<dim3(4, NZ), 256>>>(out);
}

// round 16
// speedup vs baseline: 1.1303x; 1.0209x over previous
#include <cuda_runtime.h>
#include <cuda_bf16.h>
#include <math.h>
#include <stdint.h>

// ---------------------------------------------------------------------------
// Problem constants
// ---------------------------------------------------------------------------
static constexpr int Bn = 8, Cn = 64, Hn = 256, Wn = 256;
static constexpr int HWn  = Hn * Wn;       // 65536
static constexpr int CHWn = Cn * HWn;      // 4194304
static constexpr int NZ   = Bn * Cn;       // 512
static constexpr int NTOT = 33554432;      // B*C*H*W

// ---------------------------------------------------------------------------
// Scratch (device globals: allocation-free contract)
// ---------------------------------------------------------------------------
__device__ __nv_bfloat16 g_qh[NTOT], g_ql[NTOT];
__device__ __nv_bfloat16 g_kh[NTOT], g_kl[NTOT];
__device__ __nv_bfloat16 g_vh[NTOT], g_vl[NTOT];
__device__ float         g_attn[NTOT];                 // fp32 logits [z][i][j]
__device__ __nv_bfloat16 g_ah[NTOT], g_al[NTOT];       // softmaxed attn split
__device__ __nv_bfloat16 g_Wh[3 * 4096], g_Wl[3 * 4096];  // pre-split weights

// ---------------------------------------------------------------------------
// PTX helpers — sm_80-era features only (compile clean at .target sm_103)
// ---------------------------------------------------------------------------
__device__ __forceinline__ uint32_t smem_to_u32(const void* p) {
    uint32_t a;
    asm("{ .reg .u64 t; cvta.to.shared.u64 t, %1; cvt.u32.u64 %0, t; }"
        : "=r"(a) : "l"(p));
    return a;
}

__device__ __forceinline__ void cp16(uint32_t s, const void* g) {
    asm volatile("cp.async.cg.shared.global [%0], [%1], 16;"
                 :: "r"(s), "l"(g) : "memory");
}
__device__ __forceinline__ void cp_commit() {
    asm volatile("cp.async.commit_group;" ::: "memory");
}
template <int N>
__device__ __forceinline__ void cp_wait() {
    asm volatile("cp.async.wait_group %0;" :: "n"(N) : "memory");
}

__device__ __forceinline__ void ldsm_x4(uint32_t* r, uint32_t addr) {
    asm volatile("ldmatrix.sync.aligned.m8n8.x4.shared.b16 {%0,%1,%2,%3}, [%4];"
                 : "=r"(r[0]), "=r"(r[1]), "=r"(r[2]), "=r"(r[3]) : "r"(addr));
}
__device__ __forceinline__ void ldsm_x4_t(uint32_t* r, uint32_t addr) {
    asm volatile("ldmatrix.sync.aligned.m8n8.x4.trans.shared.b16 {%0,%1,%2,%3}, [%4];"
                 : "=r"(r[0]), "=r"(r[1]), "=r"(r[2]), "=r"(r[3]) : "r"(addr));
}

__device__ __forceinline__ void mma16816(float* c, const uint32_t* a, const uint32_t* b) {
    asm volatile(
        "mma.sync.aligned.m16n8k16.row.col.f32.bf16.bf16.f32 "
        "{%0,%1,%2,%3}, {%4,%5,%6,%7}, {%8,%9}, {%0,%1,%2,%3};"
        : "+f"(c[0]), "+f"(c[1]), "+f"(c[2]), "+f"(c[3])
        : "r"(a[0]), "r"(a[1]), "r"(a[2]), "r"(a[3]), "r"(b[0]), "r"(b[1]));
}

__device__ __forceinline__ void split_bf16(float x, __nv_bfloat16& hi, __nv_bfloat16& lo) {
    hi = __float2bfloat16(x);
    lo = __float2bfloat16(x - __bfloat162float(hi));
}

// XOR swizzle for 128-byte rows (same formula as SW128 examples)
__device__ __forceinline__ uint32_t sw128(uint32_t off) {
    return off ^ ((off >> 3) & 0x70);
}

// ---------------------------------------------------------------------------
// Kernel W: one-time split of Wq/Wk/Wv into bf16 hi/lo (3 x 64 x 64)
// ---------------------------------------------------------------------------
__global__ void __launch_bounds__(256) wsplit_kernel(
    const float* __restrict__ Wq, const float* __restrict__ Wk,
    const float* __restrict__ Wv)
{
    const int t = blockIdx.x * 256 + threadIdx.x;
    if (t >= 3 * 4096) return;
    const int m = t >> 12, i = t & 4095;
    const float* src = (m == 0) ? Wq : (m == 1) ? Wk : Wv;
    __nv_bfloat16 hi, lo;
    split_bf16(src[i], hi, lo);
    g_Wh[t] = hi;
    g_Wl[t] = lo;
}

// ---------------------------------------------------------------------------
// Kernel A: tensor-core 1x1 conv. Per CTA: batch b, 64 px, all 3 matrices.
// M=o(64) x N=p(64) x K=c(64).
// Swizzled 128B-row smem layouts (SW128 xor) + DOUBLE-BUFFERED W ring:
//   prologue: cp.async W0; per m: wait -> sync -> cp W[m+1] -> compute -> epi.
// W waits for m=1,2 hide under compute; barriers 6 -> 3 per CTA.
// smem: X hi/lo 16,384 + W ring 32,768 = 49,152 B (static limit).
// ---------------------------------------------------------------------------
__global__ void __launch_bounds__(256, 2) qkv_mma_kernel(
    const float* __restrict__ x,
    const float* __restrict__ bq, const float* __restrict__ bk,
    const float* __restrict__ bv)
{
    __shared__ __align__(128) __nv_bfloat16 Xh[4096], Xl[4096];      // [c][p] 128B rows
    __shared__ __align__(128) __nv_bfloat16 Whb[2][4096], Wlb[2][4096];

    const uint32_t sXh = smem_to_u32(Xh), sXl = smem_to_u32(Xl);
    const uint32_t sWh0 = smem_to_u32(Whb[0]), sWh1 = smem_to_u32(Whb[1]);
    const uint32_t sWl0 = smem_to_u32(Wlb[0]), sWl1 = smem_to_u32(Wlb[1]);

    const int t    = threadIdx.x;
    const int lane = t & 31;
    const int wid  = t >> 5;
    const int b    = blockIdx.y;
    const int p0   = blockIdx.x * 64;

    const int o_st  = t >> 2;           // staging row (c for X, o for W)
    const int cg_st = (t & 3) * 16;     // staging col group (16 elems)

    // --- stage x tile [c=64][p=64], split to hi/lo, swizzled stores ---
    {
        const float* xrow = x + ((size_t)(b * Cn + o_st)) * HWn + p0 + cg_st;
        __nv_bfloat16 hb[16], lb[16];
        #pragma unroll
        for (int j = 0; j < 16; j += 4) {
            float4 v4 = *reinterpret_cast<const float4*>(xrow + j);
            split_bf16(v4.x, hb[j + 0], lb[j + 0]);
            split_bf16(v4.y, hb[j + 1], lb[j + 1]);
            split_bf16(v4.z, hb[j + 2], lb[j + 2]);
            split_bf16(v4.w, hb[j + 3], lb[j + 3]);
        }
        const uint32_t off0 = (uint32_t)(o_st * 128 + cg_st * 2);
        const uint32_t s0 = sw128(off0), s1 = sw128(off0 + 16);
        *reinterpret_cast<uint4*>(reinterpret_cast<char*>(Xh) + s0) = reinterpret_cast<uint4*>(hb)[0];
        *reinterpret_cast<uint4*>(reinterpret_cast<char*>(Xh) + s1) = reinterpret_cast<uint4*>(hb)[1];
        *reinterpret_cast<uint4*>(reinterpret_cast<char*>(Xl) + s0) = reinterpret_cast<uint4*>(lb)[0];
        *reinterpret_cast<uint4*>(reinterpret_cast<char*>(Xl) + s1) = reinterpret_cast<uint4*>(lb)[1];
    }

    // W staging helper offsets (same swizzled addresses every buffer)
    const uint32_t woff = (uint32_t)(o_st * 128 + cg_st * 2);
    const uint32_t w0 = sw128(woff), w1 = sw128(woff + 16);
    const int wg = o_st * 64 + cg_st;   // gmem element offset within one matrix

    // prologue: issue W0 into buffer 0
    cp16(sWh0 + w0, g_Wh + wg);
    cp16(sWh0 + w1, g_Wh + wg + 8);
    cp16(sWl0 + w0, g_Wl + wg);
    cp16(sWl0 + w1, g_Wl + wg + 8);
    cp_commit();

    const int mw = (wid & 3) * 16;   // o-offset of warp
    const int nw = (wid >> 2) * 32;  // p-offset of warp
    const int g  = lane >> 2;
    const int tg = lane & 3;

    #pragma unroll
    for (int m = 0; m < 3; m++) {
        const float* bias = (m == 0) ? bq : (m == 1) ? bk : bv;
        __nv_bfloat16* dh = (m == 0) ? g_qh : (m == 1) ? g_kh : g_vh;
        __nv_bfloat16* dl = (m == 0) ? g_ql : (m == 1) ? g_kl : g_vl;
        const uint32_t cWh = (m & 1) ? sWh1 : sWh0;
        const uint32_t cWl = (m & 1) ? sWl1 : sWl0;

        cp_wait<0>();       // W[m] arrived (this thread's chunks)
        __syncthreads();    // all threads' W[m] chunks + X stores visible

        if (m < 2) {        // prefetch W[m+1] into the other buffer
            const uint32_t nWh = (m & 1) ? sWh0 : sWh1;
            const uint32_t nWl = (m & 1) ? sWl0 : sWl1;
            const int ng = (m + 1) * 4096 + wg;
            cp16(nWh + w0, g_Wh + ng);
            cp16(nWh + w1, g_Wh + ng + 8);
            cp16(nWl + w0, g_Wl + ng);
            cp16(nWl + w1, g_Wl + ng + 8);
            cp_commit();
        }

        float acc[4][4] = {};
        #pragma unroll
        for (int ks = 0; ks < 4; ks++) {
            uint32_t ah[4], al[4];
            {   // A = W rows (o), non-trans, swizzled
                int mm = mw + (lane & 15);
                int kk = ks * 16 + ((lane >> 4) & 1) * 8;
                uint32_t rel = sw128((uint32_t)(mm * 128 + kk * 2));
                ldsm_x4(ah, cWh + rel);
                ldsm_x4(al, cWl + rel);
            }
            uint32_t bh[2][4], bl[2][4];
            #pragma unroll
            for (int np = 0; np < 2; np++) {
                int kk = ks * 16 + (lane & 7) + ((lane >> 3) & 1) * 8;
                int nn = nw + np * 16 + ((lane >> 4) & 1) * 8;
                uint32_t rel = sw128((uint32_t)(kk * 128 + nn * 2));
                ldsm_x4_t(bh[np], sXh + rel);
                ldsm_x4_t(bl[np], sXl + rel);
            }
            // term-major: consecutive mma target different accumulators
            #pragma unroll
            for (int np = 0; np < 2; np++)
                #pragma unroll
                for (int h = 0; h < 2; h++)
                    mma16816(acc[np * 2 + h], ah, bh[np] + 2 * h);
            #pragma unroll
            for (int np = 0; np < 2; np++)
                #pragma unroll
                for (int h = 0; h < 2; h++)
                    mma16816(acc[np * 2 + h], ah, bl[np] + 2 * h);
            #pragma unroll
            for (int np = 0; np < 2; np++)
                #pragma unroll
                for (int h = 0; h < 2; h++)
                    mma16816(acc[np * 2 + h], al, bh[np] + 2 * h);
        }

        // epilogue: bias add, split, store bf16x2 pairs (consecutive pixels)
        const float bo0 = bias[mw + g];
        const float bo1 = bias[mw + 8 + g];
        const size_t row0 = (size_t)(b * Cn + mw + g) * HWn + p0;
        const size_t row1 = (size_t)(b * Cn + mw + 8 + g) * HWn + p0;
        #pragma unroll
        for (int nj = 0; nj < 4; nj++) {
            const int p = nw + nj * 8 + tg * 2;
            __nv_bfloat16 h0, l0, h1, l1;
            split_bf16(acc[nj][0] + bo0, h0, l0);
            split_bf16(acc[nj][1] + bo0, h1, l1);
            __nv_bfloat162 hp, lp;
            hp.x = h0; hp.y = h1; lp.x = l0; lp.y = l1;
            *reinterpret_cast<__nv_bfloat162*>(dh + row0 + p) = hp;
            *reinterpret_cast<__nv_bfloat162*>(dl + row0 + p) = lp;
            split_bf16(acc[nj][2] + bo1, h0, l0);
            split_bf16(acc[nj][3] + bo1, h1, l1);
            hp.x = h0; hp.y = h1; lp.x = l0; lp.y = l1;
            *reinterpret_cast<__nv_bfloat162*>(dh + row1 + p) = hp;
            *reinterpret_cast<__nv_bfloat162*>(dl + row1 + p) = lp;
        }
    }
}

// ---------------------------------------------------------------------------
// Kernel B1: qtk GEMM. attn[z,i,j] = sum_h q[z,h,i] k[z,h,j].
// 128x128 CTA tile, K-chunks of 16, cp.async double-buffered static smem.
// Term-major mma ordering (acc reuse distance = 4 mma).
// ---------------------------------------------------------------------------
__global__ void __launch_bounds__(256, 2) gemm_qtk_kernel()
{
    constexpr int OFF_AL = 4352;      // A tile: [16][136] bf16 = 4352 B
    constexpr int OFF_BH = 8704;
    constexpr int OFF_BL = 13056;
    constexpr int STAGE  = 17408;

    __shared__ __align__(16) char smem[2 * STAGE];
    const uint32_t sb = smem_to_u32(smem);

    const int t    = threadIdx.x;
    const int lane = t & 31;
    const int wid  = t >> 5;
    const int z    = blockIdx.y;
    const int m0   = (blockIdx.x & 1) * 128;
    const int n0   = (blockIdx.x >> 1) * 128;
    const size_t zoff = (size_t)z * HWn;

    const __nv_bfloat16* pAh = g_qh + zoff;
    const __nv_bfloat16* pAl = g_ql + zoff;
    const __nv_bfloat16* pBh = g_kh + zoff;
    const __nv_bfloat16* pBl = g_kl + zoff;

    const int mw = (wid & 3) * 32;
    const int nw = (wid >> 2) * 64;

    float acc[2][8][4] = {};

    auto copy_chunk = [&](int kc, int stg) {
        const uint32_t s0 = sb + (uint32_t)stg * STAGE;
        const int k0  = kc * 16;
        const int row = t >> 4;
        const int c   = t & 15;
        const uint32_t so = (uint32_t)(row * 272 + c * 16);
        cp16(s0 + so,          pAh + (size_t)(k0 + row) * Wn + m0 + c * 8);
        cp16(s0 + OFF_AL + so, pAl + (size_t)(k0 + row) * Wn + m0 + c * 8);
        cp16(s0 + OFF_BH + so, pBh + (size_t)(k0 + row) * Wn + n0 + c * 8);
        cp16(s0 + OFF_BL + so, pBl + (size_t)(k0 + row) * Wn + n0 + c * 8);
    };

    auto compute = [&](int stg) {
        const uint32_t s0 = sb + (uint32_t)stg * STAGE;
        uint32_t ah[2][4], al[2][4];
        #pragma unroll
        for (int mt = 0; mt < 2; mt++) {
            int kk = (lane & 7) + ((lane >> 4) << 3);
            int mm = mw + mt * 16 + ((lane >> 3) & 1) * 8;
            uint32_t rel = (uint32_t)(kk * 272 + mm * 2);
            ldsm_x4_t(ah[mt], s0 + rel);
            ldsm_x4_t(al[mt], s0 + OFF_AL + rel);
        }
        #pragma unroll
        for (int np = 0; np < 4; np++) {
            int kk = (lane & 7) + ((lane >> 3) & 1) * 8;
            int nn = nw + np * 16 + ((lane >> 4) & 1) * 8;
            uint32_t rel = (uint32_t)(kk * 272 + nn * 2);
            uint32_t bh[4], bl[4];
            ldsm_x4_t(bh, s0 + OFF_BH + rel);
            ldsm_x4_t(bl, s0 + OFF_BL + rel);
            #pragma unroll
            for (int mt = 0; mt < 2; mt++)
                #pragma unroll
                for (int h = 0; h < 2; h++)
                    mma16816(acc[mt][np * 2 + h], ah[mt], bh + 2 * h);
            #pragma unroll
            for (int mt = 0; mt < 2; mt++)
                #pragma unroll
                for (int h = 0; h < 2; h++)
                    mma16816(acc[mt][np * 2 + h], ah[mt], bl + 2 * h);
            #pragma unroll
            for (int mt = 0; mt < 2; mt++)
                #pragma unroll
                for (int h = 0; h < 2; h++)
                    mma16816(acc[mt][np * 2 + h], al[mt], bh + 2 * h);
        }
    };

    copy_chunk(0, 0);
    cp_commit();
    for (int kc = 0; kc < 16; kc++) {
        cp_wait<0>();
        __syncthreads();
        if (kc < 15) { copy_chunk(kc + 1, (kc + 1) & 1); cp_commit(); }
        compute(kc & 1);
    }

    const int g  = lane >> 2;
    const int tg = lane & 3;
    #pragma unroll
    for (int mt = 0; mt < 2; mt++) {
        const int r0 = m0 + mw + mt * 16 + g;
        #pragma unroll
        for (int nj = 0; nj < 8; nj++) {
            const int col = n0 + nw + nj * 8 + tg * 2;
            *reinterpret_cast<float2*>(g_attn + zoff + (size_t)r0 * Wn + col) =
                make_float2(acc[mt][nj][0], acc[mt][nj][1]);
            *reinterpret_cast<float2*>(g_attn + zoff + (size_t)(r0 + 8) * Wn + col) =
                make_float2(acc[mt][nj][2], acc[mt][nj][3]);
        }
    }
}

// ---------------------------------------------------------------------------
// Kernel B2: av GEMM. out[z,i,j] = sum_m attn[z,i,m] v[z,m,j].
// ---------------------------------------------------------------------------
__global__ void __launch_bounds__(256, 2) gemm_av_kernel(float* __restrict__ out)
{
    constexpr int APITCH = 48;
    constexpr int OFF_AL = 6144;
    constexpr int OFF_BH = 12288;
    constexpr int OFF_BL = 16640;
    constexpr int STAGE  = 20992;

    __shared__ __align__(16) char smem[2 * STAGE];
    const uint32_t sb = smem_to_u32(smem);

    const int t    = threadIdx.x;
    const int lane = t & 31;
    const int wid  = t >> 5;
    const int z    = blockIdx.y;
    const int m0   = (blockIdx.x & 1) * 128;
    const int n0   = (blockIdx.x >> 1) * 128;
    const size_t zoff = (size_t)z * HWn;

    const __nv_bfloat16* pAh = g_ah + zoff;
    const __nv_bfloat16* pAl = g_al + zoff;
    const __nv_bfloat16* pBh = g_vh + zoff;
    const __nv_bfloat16* pBl = g_vl + zoff;

    const int mw = (wid & 3) * 32;
    const int nw = (wid >> 2) * 64;

    float acc[2][8][4] = {};

    auto copy_chunk = [&](int kc, int stg) {
        const uint32_t s0 = sb + (uint32_t)stg * STAGE;
        const int k0 = kc * 16;
        {
            const int row = t >> 1;
            const int c   = t & 1;
            const uint32_t so = (uint32_t)(row * APITCH + c * 16);
            cp16(s0 + so,          pAh + (size_t)(m0 + row) * Wn + k0 + c * 8);
            cp16(s0 + OFF_AL + so, pAl + (size_t)(m0 + row) * Wn + k0 + c * 8);
        }
        {
            const int row = t >> 4;
            const int c   = t & 15;
            const uint32_t so = (uint32_t)(row * 272 + c * 16);
            cp16(s0 + OFF_BH + so, pBh + (size_t)(k0 + row) * Wn + n0 + c * 8);
            cp16(s0 + OFF_BL + so, pBl + (size_t)(k0 + row) * Wn + n0 + c * 8);
        }
    };

    auto compute = [&](int stg) {
        const uint32_t s0 = sb + (uint32_t)stg * STAGE;
        uint32_t ah[2][4], al[2][4];
        #pragma unroll
        for (int mt = 0; mt < 2; mt++) {
            int mm = mw + mt * 16 + (lane & 15);
            int kk = ((lane >> 4) & 1) * 8;
            uint32_t rel = (uint32_t)(mm * APITCH + kk * 2);
            ldsm_x4(ah[mt], s0 + rel);
            ldsm_x4(al[mt], s0 + OFF_AL + rel);
        }
        #pragma unroll
        for (int np = 0; np < 4; np++) {
            int kk = (lane & 7) + ((lane >> 3) & 1) * 8;
            int nn = nw + np * 16 + ((lane >> 4) & 1) * 8;
            uint32_t rel = (uint32_t)(kk * 272 + nn * 2);
            uint32_t bh[4], bl[4];
            ldsm_x4_t(bh, s0 + OFF_BH + rel);
            ldsm_x4_t(bl, s0 + OFF_BL + rel);
            #pragma unroll
            for (int mt = 0; mt < 2; mt++)
                #pragma unroll
                for (int h = 0; h < 2; h++)
                    mma16816(acc[mt][np * 2 + h], ah[mt], bh + 2 * h);
            #pragma unroll
            for (int mt = 0; mt < 2; mt++)
                #pragma unroll
                for (int h = 0; h < 2; h++)
                    mma16816(acc[mt][np * 2 + h], ah[mt], bl + 2 * h);
            #pragma unroll
            for (int mt = 0; mt < 2; mt++)
                #pragma unroll
                for (int h = 0; h < 2; h++)
                    mma16816(acc[mt][np * 2 + h], al[mt], bh + 2 * h);
        }
    };

    copy_chunk(0, 0);
    cp_commit();
    for (int kc = 0; kc < 16; kc++) {
        cp_wait<0>();
        __syncthreads();
        if (kc < 15) { copy_chunk(kc + 1, (kc + 1) & 1); cp_commit(); }
        compute(kc & 1);
    }

    const int g  = lane >> 2;
    const int tg = lane & 3;
    #pragma unroll
    for (int mt = 0; mt < 2; mt++) {
        const int r0 = m0 + mw + mt * 16 + g;
        #pragma unroll
        for (int nj = 0; nj < 8; nj++) {
            const int col = n0 + nw + nj * 8 + tg * 2;
            *reinterpret_cast<float2*>(out + zoff + (size_t)r0 * Wn + col) =
                make_float2(acc[mt][nj][0], acc[mt][nj][1]);
            *reinterpret_cast<float2*>(out + zoff + (size_t)(r0 + 8) * Wn + col) =
                make_float2(acc[mt][nj][2], acc[mt][nj][3]);
        }
    }
}

// ---------------------------------------------------------------------------
// Kernel C: softmax over channel axis (fp32 in, bf16 hi/lo out)
// ---------------------------------------------------------------------------
__global__ void __launch_bounds__(256) softmax_split_kernel()
{
    const int idx = blockIdx.x * 256 + threadIdx.x;   // 0 .. B*HW-1
    const int b   = idx >> 16;
    const int ij  = idx & 65535;
    const size_t base = (size_t)b * CHWn + ij;

    float v[64];
    float mx = -INFINITY;
    #pragma unroll
    for (int c = 0; c < 64; c++) {
        v[c] = g_attn[base + (size_t)c * HWn];
        mx = fmaxf(mx, v[c]);
    }
    float s = 0.0f;
    #pragma unroll
    for (int c = 0; c < 64; c++) {
        v[c] = __expf(v[c] - mx);
        s += v[c];
    }
    const float inv = 1.0f / s;
    #pragma unroll
    for (int c = 0; c < 64; c++) {
        float p = v[c] * inv;
        __nv_bfloat16 hi, lo;
        split_bf16(p, hi, lo);
        g_ah[base + (size_t)c * HWn] = hi;
        g_al[base + (size_t)c * HWn] = lo;
    }
}

// ---------------------------------------------------------------------------
// Launch — no dynamic smem, no attribute calls, plain default-stream launches.
// ---------------------------------------------------------------------------
extern "C" void kernel_launch(void* const* d_in, const int* in_sizes, int n_in,
                              void* d_out, int out_size)
{
    const float* x  = (const float*)d_in[0];
    const float* Wq = (const float*)d_in[1];
    const float* bq = (const float*)d_in[2];
    const float* Wk = (const float*)d_in[3];
    const float* bk = (const float*)d_in[4];
    const float* Wv = (const float*)d_in[5];
    const float* bv = (const float*)d_in[6];
    float* out = (float*)d_out;

    // 0) split weights to bf16 hi/lo (tiny)
    wsplit_kernel<<<48, 256>>>(Wq, Wk, Wv);

    // 1) q,k,v = 1x1 conv(x) on tensor cores, double-buffered W ring
    qkv_mma_kernel<<<dim3(HWn / 64, Bn), 256>>>(x, bq, bk, bv);

    // 2) attn logits: attn[z,i,j] = sum_h q[z,h,i] k[z,h,j]
    gemm_qtk_kernel<<<dim3(4, NZ), 256>>>();

    // 3) softmax over channels, emit bf16 hi/lo ([i][m] row-major for next GEMM)
    softmax_split_kernel<<<(Bn * HWn) / 256, 256>>>();

    // 4) out[z,i,j] = sum_m attn[z,i,m] v[z,m,j]
    gemm_av_kernel<<<dim3(4, NZ), 256>>>(out);
}

// round 17
// speedup vs baseline: 1.1406x; 1.0091x over previous
#include <cuda_runtime.h>
#include <cuda_bf16.h>
#include <math.h>
#include <stdint.h>

// ---------------------------------------------------------------------------
// Problem constants
// ---------------------------------------------------------------------------
static constexpr int Bn = 8, Cn = 64, Hn = 256, Wn = 256;
static constexpr int HWn  = Hn * Wn;       // 65536
static constexpr int CHWn = Cn * HWn;      // 4194304
static constexpr int NZ   = Bn * Cn;       // 512
static constexpr int NTOT = 33554432;      // B*C*H*W

// ---------------------------------------------------------------------------
// Scratch (device globals: allocation-free contract)
// ---------------------------------------------------------------------------
__device__ __nv_bfloat16 g_qh[NTOT], g_ql[NTOT];
__device__ __nv_bfloat16 g_kh[NTOT], g_kl[NTOT];
__device__ __nv_bfloat16 g_vh[NTOT], g_vl[NTOT];
__device__ float         g_attn[NTOT];                 // fp32 logits [z][i][j]
__device__ __nv_bfloat16 g_ah[NTOT], g_al[NTOT];       // softmaxed attn split
__device__ __nv_bfloat16 g_Wh[3 * 4096], g_Wl[3 * 4096];  // pre-split weights

// ---------------------------------------------------------------------------
// PTX helpers — sm_80-era features only (compile clean at .target sm_103)
// ---------------------------------------------------------------------------
__device__ __forceinline__ uint32_t smem_to_u32(const void* p) {
    uint32_t a;
    asm("{ .reg .u64 t; cvta.to.shared.u64 t, %1; cvt.u32.u64 %0, t; }"
        : "=r"(a) : "l"(p));
    return a;
}

__device__ __forceinline__ void cp16(uint32_t s, const void* g) {
    asm volatile("cp.async.cg.shared.global [%0], [%1], 16;"
                 :: "r"(s), "l"(g) : "memory");
}
__device__ __forceinline__ void cp_commit() {
    asm volatile("cp.async.commit_group;" ::: "memory");
}
template <int N>
__device__ __forceinline__ void cp_wait() {
    asm volatile("cp.async.wait_group %0;" :: "n"(N) : "memory");
}

__device__ __forceinline__ void ldsm_x4(uint32_t* r, uint32_t addr) {
    asm volatile("ldmatrix.sync.aligned.m8n8.x4.shared.b16 {%0,%1,%2,%3}, [%4];"
                 : "=r"(r[0]), "=r"(r[1]), "=r"(r[2]), "=r"(r[3]) : "r"(addr));
}
__device__ __forceinline__ void ldsm_x4_t(uint32_t* r, uint32_t addr) {
    asm volatile("ldmatrix.sync.aligned.m8n8.x4.trans.shared.b16 {%0,%1,%2,%3}, [%4];"
                 : "=r"(r[0]), "=r"(r[1]), "=r"(r[2]), "=r"(r[3]) : "r"(addr));
}

__device__ __forceinline__ void mma16816(float* c, const uint32_t* a, const uint32_t* b) {
    asm volatile(
        "mma.sync.aligned.m16n8k16.row.col.f32.bf16.bf16.f32 "
        "{%0,%1,%2,%3}, {%4,%5,%6,%7}, {%8,%9}, {%0,%1,%2,%3};"
        : "+f"(c[0]), "+f"(c[1]), "+f"(c[2]), "+f"(c[3])
        : "r"(a[0]), "r"(a[1]), "r"(a[2]), "r"(a[3]), "r"(b[0]), "r"(b[1]));
}

__device__ __forceinline__ void split_bf16(float x, __nv_bfloat16& hi, __nv_bfloat16& lo) {
    hi = __float2bfloat16(x);
    lo = __float2bfloat16(x - __bfloat162float(hi));
}

// XOR swizzle for 128-byte rows (same formula as SW128 examples)
__device__ __forceinline__ uint32_t sw128(uint32_t off) {
    return off ^ ((off >> 3) & 0x70);
}

// ---------------------------------------------------------------------------
// Kernel W: one-time split of Wq/Wk/Wv into bf16 hi/lo (3 x 64 x 64)
// ---------------------------------------------------------------------------
__global__ void __launch_bounds__(256) wsplit_kernel(
    const float* __restrict__ Wq, const float* __restrict__ Wk,
    const float* __restrict__ Wv)
{
    const int t = blockIdx.x * 256 + threadIdx.x;
    if (t >= 3 * 4096) return;
    const int m = t >> 12, i = t & 4095;
    const float* src = (m == 0) ? Wq : (m == 1) ? Wk : Wv;
    __nv_bfloat16 hi, lo;
    split_bf16(src[i], hi, lo);
    g_Wh[t] = hi;
    g_Wl[t] = lo;
}

// ---------------------------------------------------------------------------
// Kernel A: tensor-core 1x1 conv. Per CTA: batch b, 64 px, all 3 matrices.
// M=o(64) x N=p(64) x K=c(64). Swizzled 128B-row smem (SW128 xor).
// SINGLE W buffer (16 KB) + X (16 KB) = 32,768 B/CTA -> 3 CTAs/SM.
// Scheduling hides W waits: W0 issued before X staging; W[m+1] issued
// before epilogue[m] so its L2 latency hides under the gmem stores.
// ---------------------------------------------------------------------------
__global__ void __launch_bounds__(256, 3) qkv_mma_kernel(
    const float* __restrict__ x,
    const float* __restrict__ bq, const float* __restrict__ bk,
    const float* __restrict__ bv)
{
    __shared__ __align__(128) __nv_bfloat16 Xh[4096], Xl[4096];  // [c][p] 128B rows
    __shared__ __align__(128) __nv_bfloat16 Wh[4096], Wl[4096];  // [o][c] 128B rows

    const uint32_t sXh = smem_to_u32(Xh), sXl = smem_to_u32(Xl);
    const uint32_t sWh = smem_to_u32(Wh), sWl = smem_to_u32(Wl);

    const int t    = threadIdx.x;
    const int lane = t & 31;
    const int wid  = t >> 5;
    const int b    = blockIdx.y;
    const int p0   = blockIdx.x * 64;

    const int o_st  = t >> 2;           // staging row (c for X, o for W)
    const int cg_st = (t & 3) * 16;     // staging col group (16 elems)

    // W staging offsets (same swizzled addresses every m)
    const uint32_t woff = (uint32_t)(o_st * 128 + cg_st * 2);
    const uint32_t w0 = sw128(woff), w1 = sw128(woff + 16);
    const int wg = o_st * 64 + cg_st;   // gmem elem offset within one matrix

    // prologue: issue W0 FIRST so its latency hides under X staging
    cp16(sWh + w0, g_Wh + wg);
    cp16(sWh + w1, g_Wh + wg + 8);
    cp16(sWl + w0, g_Wl + wg);
    cp16(sWl + w1, g_Wl + wg + 8);
    cp_commit();

    // --- stage x tile [c=64][p=64], split to hi/lo, swizzled stores ---
    {
        const float* xrow = x + ((size_t)(b * Cn + o_st)) * HWn + p0 + cg_st;
        __nv_bfloat16 hb[16], lb[16];
        #pragma unroll
        for (int j = 0; j < 16; j += 4) {
            float4 v4 = *reinterpret_cast<const float4*>(xrow + j);
            split_bf16(v4.x, hb[j + 0], lb[j + 0]);
            split_bf16(v4.y, hb[j + 1], lb[j + 1]);
            split_bf16(v4.z, hb[j + 2], lb[j + 2]);
            split_bf16(v4.w, hb[j + 3], lb[j + 3]);
        }
        const uint32_t off0 = (uint32_t)(o_st * 128 + cg_st * 2);
        const uint32_t s0 = sw128(off0), s1 = sw128(off0 + 16);
        *reinterpret_cast<uint4*>(reinterpret_cast<char*>(Xh) + s0) = reinterpret_cast<uint4*>(hb)[0];
        *reinterpret_cast<uint4*>(reinterpret_cast<char*>(Xh) + s1) = reinterpret_cast<uint4*>(hb)[1];
        *reinterpret_cast<uint4*>(reinterpret_cast<char*>(Xl) + s0) = reinterpret_cast<uint4*>(lb)[0];
        *reinterpret_cast<uint4*>(reinterpret_cast<char*>(Xl) + s1) = reinterpret_cast<uint4*>(lb)[1];
    }

    const int mw = (wid & 3) * 16;   // o-offset of warp
    const int nw = (wid >> 2) * 32;  // p-offset of warp
    const int g  = lane >> 2;
    const int tg = lane & 3;

    #pragma unroll
    for (int m = 0; m < 3; m++) {
        const float* bias = (m == 0) ? bq : (m == 1) ? bk : bv;
        __nv_bfloat16* dh = (m == 0) ? g_qh : (m == 1) ? g_kh : g_vh;
        __nv_bfloat16* dl = (m == 0) ? g_ql : (m == 1) ? g_kl : g_vl;

        cp_wait<0>();       // W[m] arrived (this thread's chunks)
        __syncthreads();    // all threads' W[m] chunks + X stores visible

        float acc[4][4] = {};
        #pragma unroll
        for (int ks = 0; ks < 4; ks++) {
            uint32_t ah[4], al[4];
            {   // A = W rows (o), non-trans, swizzled
                int mm = mw + (lane & 15);
                int kk = ks * 16 + ((lane >> 4) & 1) * 8;
                uint32_t rel = sw128((uint32_t)(mm * 128 + kk * 2));
                ldsm_x4(ah, sWh + rel);
                ldsm_x4(al, sWl + rel);
            }
            uint32_t bh[2][4], bl[2][4];
            #pragma unroll
            for (int np = 0; np < 2; np++) {
                int kk = ks * 16 + (lane & 7) + ((lane >> 3) & 1) * 8;
                int nn = nw + np * 16 + ((lane >> 4) & 1) * 8;
                uint32_t rel = sw128((uint32_t)(kk * 128 + nn * 2));
                ldsm_x4_t(bh[np], sXh + rel);
                ldsm_x4_t(bl[np], sXl + rel);
            }
            // term-major: consecutive mma target different accumulators
            #pragma unroll
            for (int np = 0; np < 2; np++)
                #pragma unroll
                for (int h = 0; h < 2; h++)
                    mma16816(acc[np * 2 + h], ah, bh[np] + 2 * h);
            #pragma unroll
            for (int np = 0; np < 2; np++)
                #pragma unroll
                for (int h = 0; h < 2; h++)
                    mma16816(acc[np * 2 + h], ah, bl[np] + 2 * h);
            #pragma unroll
            for (int np = 0; np < 2; np++)
                #pragma unroll
                for (int h = 0; h < 2; h++)
                    mma16816(acc[np * 2 + h], al, bh[np] + 2 * h);
        }

        if (m < 2) {
            __syncthreads();    // all warps done ldsm-reading W[m]
            const int ng = (m + 1) * 4096 + wg;
            cp16(sWh + w0, g_Wh + ng);
            cp16(sWh + w1, g_Wh + ng + 8);
            cp16(sWl + w0, g_Wl + ng);
            cp16(sWl + w1, g_Wl + ng + 8);
            cp_commit();        // W[m+1] latency hides under epilogue below
        }

        // epilogue: bias add, split, store bf16x2 pairs (consecutive pixels)
        const float bo0 = bias[mw + g];
        const float bo1 = bias[mw + 8 + g];
        const size_t row0 = (size_t)(b * Cn + mw + g) * HWn + p0;
        const size_t row1 = (size_t)(b * Cn + mw + 8 + g) * HWn + p0;
        #pragma unroll
        for (int nj = 0; nj < 4; nj++) {
            const int p = nw + nj * 8 + tg * 2;
            __nv_bfloat16 h0, l0, h1, l1;
            split_bf16(acc[nj][0] + bo0, h0, l0);
            split_bf16(acc[nj][1] + bo0, h1, l1);
            __nv_bfloat162 hp, lp;
            hp.x = h0; hp.y = h1; lp.x = l0; lp.y = l1;
            *reinterpret_cast<__nv_bfloat162*>(dh + row0 + p) = hp;
            *reinterpret_cast<__nv_bfloat162*>(dl + row0 + p) = lp;
            split_bf16(acc[nj][2] + bo1, h0, l0);
            split_bf16(acc[nj][3] + bo1, h1, l1);
            hp.x = h0; hp.y = h1; lp.x = l0; lp.y = l1;
            *reinterpret_cast<__nv_bfloat162*>(dh + row1 + p) = hp;
            *reinterpret_cast<__nv_bfloat162*>(dl + row1 + p) = lp;
        }
    }
}

// ---------------------------------------------------------------------------
// Kernel B1: qtk GEMM. attn[z,i,j] = sum_h q[z,h,i] k[z,h,j].
// 128x128 CTA tile, K-chunks of 16, cp.async double-buffered static smem.
// Term-major mma ordering (acc reuse distance = 4 mma).
// ---------------------------------------------------------------------------
__global__ void __launch_bounds__(256, 2) gemm_qtk_kernel()
{
    constexpr int OFF_AL = 4352;      // A tile: [16][136] bf16 = 4352 B
    constexpr int OFF_BH = 8704;
    constexpr int OFF_BL = 13056;
    constexpr int STAGE  = 17408;

    __shared__ __align__(16) char smem[2 * STAGE];
    const uint32_t sb = smem_to_u32(smem);

    const int t    = threadIdx.x;
    const int lane = t & 31;
    const int wid  = t >> 5;
    const int z    = blockIdx.y;
    const int m0   = (blockIdx.x & 1) * 128;
    const int n0   = (blockIdx.x >> 1) * 128;
    const size_t zoff = (size_t)z * HWn;

    const __nv_bfloat16* pAh = g_qh + zoff;
    const __nv_bfloat16* pAl = g_ql + zoff;
    const __nv_bfloat16* pBh = g_kh + zoff;
    const __nv_bfloat16* pBl = g_kl + zoff;

    const int mw = (wid & 3) * 32;
    const int nw = (wid >> 2) * 64;

    float acc[2][8][4] = {};

    auto copy_chunk = [&](int kc, int stg) {
        const uint32_t s0 = sb + (uint32_t)stg * STAGE;
        const int k0  = kc * 16;
        const int row = t >> 4;
        const int c   = t & 15;
        const uint32_t so = (uint32_t)(row * 272 + c * 16);
        cp16(s0 + so,          pAh + (size_t)(k0 + row) * Wn + m0 + c * 8);
        cp16(s0 + OFF_AL + so, pAl + (size_t)(k0 + row) * Wn + m0 + c * 8);
        cp16(s0 + OFF_BH + so, pBh + (size_t)(k0 + row) * Wn + n0 + c * 8);
        cp16(s0 + OFF_BL + so, pBl + (size_t)(k0 + row) * Wn + n0 + c * 8);
    };

    auto compute = [&](int stg) {
        const uint32_t s0 = sb + (uint32_t)stg * STAGE;
        uint32_t ah[2][4], al[2][4];
        #pragma unroll
        for (int mt = 0; mt < 2; mt++) {
            int kk = (lane & 7) + ((lane >> 4) << 3);
            int mm = mw + mt * 16 + ((lane >> 3) & 1) * 8;
            uint32_t rel = (uint32_t)(kk * 272 + mm * 2);
            ldsm_x4_t(ah[mt], s0 + rel);
            ldsm_x4_t(al[mt], s0 + OFF_AL + rel);
        }
        #pragma unroll
        for (int np = 0; np < 4; np++) {
            int kk = (lane & 7) + ((lane >> 3) & 1) * 8;
            int nn = nw + np * 16 + ((lane >> 4) & 1) * 8;
            uint32_t rel = (uint32_t)(kk * 272 + nn * 2);
            uint32_t bh[4], bl[4];
            ldsm_x4_t(bh, s0 + OFF_BH + rel);
            ldsm_x4_t(bl, s0 + OFF_BL + rel);
            #pragma unroll
            for (int mt = 0; mt < 2; mt++)
                #pragma unroll
                for (int h = 0; h < 2; h++)
                    mma16816(acc[mt][np * 2 + h], ah[mt], bh + 2 * h);
            #pragma unroll
            for (int mt = 0; mt < 2; mt++)
                #pragma unroll
                for (int h = 0; h < 2; h++)
                    mma16816(acc[mt][np * 2 + h], ah[mt], bl + 2 * h);
            #pragma unroll
            for (int mt = 0; mt < 2; mt++)
                #pragma unroll
                for (int h = 0; h < 2; h++)
                    mma16816(acc[mt][np * 2 + h], al[mt], bh + 2 * h);
        }
    };

    copy_chunk(0, 0);
    cp_commit();
    for (int kc = 0; kc < 16; kc++) {
        cp_wait<0>();
        __syncthreads();
        if (kc < 15) { copy_chunk(kc + 1, (kc + 1) & 1); cp_commit(); }
        compute(kc & 1);
    }

    const int g  = lane >> 2;
    const int tg = lane & 3;
    #pragma unroll
    for (int mt = 0; mt < 2; mt++) {
        const int r0 = m0 + mw + mt * 16 + g;
        #pragma unroll
        for (int nj = 0; nj < 8; nj++) {
            const int col = n0 + nw + nj * 8 + tg * 2;
            *reinterpret_cast<float2*>(g_attn + zoff + (size_t)r0 * Wn + col) =
                make_float2(acc[mt][nj][0], acc[mt][nj][1]);
            *reinterpret_cast<float2*>(g_attn + zoff + (size_t)(r0 + 8) * Wn + col) =
                make_float2(acc[mt][nj][2], acc[mt][nj][3]);
        }
    }
}

// ---------------------------------------------------------------------------
// Kernel B2: av GEMM. out[z,i,j] = sum_m attn[z,i,m] v[z,m,j].
// ---------------------------------------------------------------------------
__global__ void __launch_bounds__(256, 2) gemm_av_kernel(float* __restrict__ out)
{
    constexpr int APITCH = 48;
    constexpr int OFF_AL = 6144;
    constexpr int OFF_BH = 12288;
    constexpr int OFF_BL = 16640;
    constexpr int STAGE  = 20992;

    __shared__ __align__(16) char smem[2 * STAGE];
    const uint32_t sb = smem_to_u32(smem);

    const int t    = threadIdx.x;
    const int lane = t & 31;
    const int wid  = t >> 5;
    const int z    = blockIdx.y;
    const int m0   = (blockIdx.x & 1) * 128;
    const int n0   = (blockIdx.x >> 1) * 128;
    const size_t zoff = (size_t)z * HWn;

    const __nv_bfloat16* pAh = g_ah + zoff;
    const __nv_bfloat16* pAl = g_al + zoff;
    const __nv_bfloat16* pBh = g_vh + zoff;
    const __nv_bfloat16* pBl = g_vl + zoff;

    const int mw = (wid & 3) * 32;
    const int nw = (wid >> 2) * 64;

    float acc[2][8][4] = {};

    auto copy_chunk = [&](int kc, int stg) {
        const uint32_t s0 = sb + (uint32_t)stg * STAGE;
        const int k0 = kc * 16;
        {
            const int row = t >> 1;
            const int c   = t & 1;
            const uint32_t so = (uint32_t)(row * APITCH + c * 16);
            cp16(s0 + so,          pAh + (size_t)(m0 + row) * Wn + k0 + c * 8);
            cp16(s0 + OFF_AL + so, pAl + (size_t)(m0 + row) * Wn + k0 + c * 8);
        }
        {
            const int row = t >> 4;
            const int c   = t & 15;
            const uint32_t so = (uint32_t)(row * 272 + c * 16);
            cp16(s0 + OFF_BH + so, pBh + (size_t)(k0 + row) * Wn + n0 + c * 8);
            cp16(s0 + OFF_BL + so, pBl + (size_t)(k0 + row) * Wn + n0 + c * 8);
        }
    };

    auto compute = [&](int stg) {
        const uint32_t s0 = sb + (uint32_t)stg * STAGE;
        uint32_t ah[2][4], al[2][4];
        #pragma unroll
        for (int mt = 0; mt < 2; mt++) {
            int mm = mw + mt * 16 + (lane & 15);
            int kk = ((lane >> 4) & 1) * 8;
            uint32_t rel = (uint32_t)(mm * APITCH + kk * 2);
            ldsm_x4(ah[mt], s0 + rel);
            ldsm_x4(al[mt], s0 + OFF_AL + rel);
        }
        #pragma unroll
        for (int np = 0; np < 4; np++) {
            int kk = (lane & 7) + ((lane >> 3) & 1) * 8;
            int nn = nw + np * 16 + ((lane >> 4) & 1) * 8;
            uint32_t rel = (uint32_t)(kk * 272 + nn * 2);
            uint32_t bh[4], bl[4];
            ldsm_x4_t(bh, s0 + OFF_BH + rel);
            ldsm_x4_t(bl, s0 + OFF_BL + rel);
            #pragma unroll
            for (int mt = 0; mt < 2; mt++)
                #pragma unroll
                for (int h = 0; h < 2; h++)
                    mma16816(acc[mt][np * 2 + h], ah[mt], bh + 2 * h);
            #pragma unroll
            for (int mt = 0; mt < 2; mt++)
                #pragma unroll
                for (int h = 0; h < 2; h++)
                    mma16816(acc[mt][np * 2 + h], ah[mt], bl + 2 * h);
            #pragma unroll
            for (int mt = 0; mt < 2; mt++)
                #pragma unroll
                for (int h = 0; h < 2; h++)
                    mma16816(acc[mt][np * 2 + h], al[mt], bh + 2 * h);
        }
    };

    copy_chunk(0, 0);
    cp_commit();
    for (int kc = 0; kc < 16; kc++) {
        cp_wait<0>();
        __syncthreads();
        if (kc < 15) { copy_chunk(kc + 1, (kc + 1) & 1); cp_commit(); }
        compute(kc & 1);
    }

    const int g  = lane >> 2;
    const int tg = lane & 3;
    #pragma unroll
    for (int mt = 0; mt < 2; mt++) {
        const int r0 = m0 + mw + mt * 16 + g;
        #pragma unroll
        for (int nj = 0; nj < 8; nj++) {
            const int col = n0 + nw + nj * 8 + tg * 2;
            *reinterpret_cast<float2*>(out + zoff + (size_t)r0 * Wn + col) =
                make_float2(acc[mt][nj][0], acc[mt][nj][1]);
            *reinterpret_cast<float2*>(out + zoff + (size_t)(r0 + 8) * Wn + col) =
                make_float2(acc[mt][nj][2], acc[mt][nj][3]);
        }
    }
}

// ---------------------------------------------------------------------------
// Kernel C: softmax over channel axis (fp32 in, bf16 hi/lo out)
// ---------------------------------------------------------------------------
__global__ void __launch_bounds__(256) softmax_split_kernel()
{
    const int idx = blockIdx.x * 256 + threadIdx.x;   // 0 .. B*HW-1
    const int b   = idx >> 16;
    const int ij  = idx & 65535;
    const size_t base = (size_t)b * CHWn + ij;

    float v[64];
    float mx = -INFINITY;
    #pragma unroll
    for (int c = 0; c < 64; c++) {
        v[c] = g_attn[base + (size_t)c * HWn];
        mx = fmaxf(mx, v[c]);
    }
    float s = 0.0f;
    #pragma unroll
    for (int c = 0; c < 64; c++) {
        v[c] = __expf(v[c] - mx);
        s += v[c];
    }
    const float inv = 1.0f / s;
    #pragma unroll
    for (int c = 0; c < 64; c++) {
        float p = v[c] * inv;
        __nv_bfloat16 hi, lo;
        split_bf16(p, hi, lo);
        g_ah[base + (size_t)c * HWn] = hi;
        g_al[base + (size_t)c * HWn] = lo;
    }
}

// ---------------------------------------------------------------------------
// Launch — no dynamic smem, no attribute calls, plain default-stream launches.
// ---------------------------------------------------------------------------
extern "C" void kernel_launch(void* const* d_in, const int* in_sizes, int n_in,
                              void* d_out, int out_size)
{
    const float* x  = (const float*)d_in[0];
    const float* Wq = (const float*)d_in[1];
    const float* bq = (const float*)d_in[2];
    const float* Wk = (const float*)d_in[3];
    const float* bk = (const float*)d_in[4];
    const float* Wv = (const float*)d_in[5];
    const float* bv = (const float*)d_in[6];
    float* out = (float*)d_out;

    // 0) split weights to bf16 hi/lo (tiny)
    wsplit_kernel<<<48, 256>>>(Wq, Wk, Wv);

    // 1) q,k,v = 1x1 conv(x) on tensor cores, 3 CTAs/SM, scheduled W staging
    qkv_mma_kernel<<<dim3(HWn / 64, Bn), 256>>>(x, bq, bk, bv);

    // 2) attn logits: attn[z,i,j] = sum_h q[z,h,i] k[z,h,j]
    gemm_qtk_kernel<<<dim3(4, NZ), 256>>>();

    // 3) softmax over channels, emit bf16 hi/lo ([i][m] row-major for next GEMM)
    softmax_split_kernel<<<(Bn * HWn) / 256, 256>>>();

    // 4) out[z,i,j] = sum_m attn[z,i,m] v[z,m,j]
    gemm_av_kernel<<<dim3(4, NZ), 256>>>(out);
}